// round 2
// baseline (speedup 1.0000x reference)
#include <cuda_runtime.h>
#include <math.h>

#define B_  4
#define T_  2048
#define D_  1024
#define H_  8
#define DK_ 128
#define P_  (2*T_-1)
#define BT_ (B_*T_)

// ---------------- scratch (device globals: allocation-free) ----------------
static __device__ float g_q [(size_t)BT_ * D_];
static __device__ float g_k [(size_t)BT_ * D_];
static __device__ float g_v [(size_t)BT_ * D_];
static __device__ float g_p [(size_t)P_  * D_];
static __device__ float g_s [(size_t)B_ * H_ * T_ * T_];   // 512 MB scores/attn
static __device__ float g_ao[(size_t)BT_ * D_];

// ---------------- generic NT GEMM: C[M,N] = A[M,K] @ B[N,K]^T ----------------
// BM=BN=128, BK=8, 256 threads, 8x8 per thread.
__global__ void __launch_bounds__(256) gemm_nt(const float* __restrict__ A,
                                               const float* __restrict__ B,
                                               float* __restrict__ C,
                                               int M, int N, int K) {
    __shared__ float As[8][128];
    __shared__ float Bs[8][128];
    int tid = threadIdx.x;
    int tx = tid & 15, ty = tid >> 4;
    int m0 = blockIdx.y * 128, n0 = blockIdx.x * 128;
    float acc[8][8];
    #pragma unroll
    for (int i = 0; i < 8; i++)
        #pragma unroll
        for (int j = 0; j < 8; j++) acc[i][j] = 0.f;

    int r  = tid >> 1;
    int c4 = (tid & 1) * 4;
    for (int k0 = 0; k0 < K; k0 += 8) {
        // load A,B tiles as float4 along K, transpose into [k][row] smem
        float4 av = make_float4(0.f, 0.f, 0.f, 0.f);
        float4 bv = make_float4(0.f, 0.f, 0.f, 0.f);
        int m = m0 + r, n = n0 + r;
        if (m < M) av = *(const float4*)&A[(size_t)m * K + k0 + c4];
        if (n < N) bv = *(const float4*)&B[(size_t)n * K + k0 + c4];
        As[c4 + 0][r] = av.x; As[c4 + 1][r] = av.y;
        As[c4 + 2][r] = av.z; As[c4 + 3][r] = av.w;
        Bs[c4 + 0][r] = bv.x; Bs[c4 + 1][r] = bv.y;
        Bs[c4 + 2][r] = bv.z; Bs[c4 + 3][r] = bv.w;
        __syncthreads();
        #pragma unroll
        for (int kk = 0; kk < 8; kk++) {
            float4 a0 = *(const float4*)&As[kk][ty * 8];
            float4 a1 = *(const float4*)&As[kk][ty * 8 + 4];
            float4 b0 = *(const float4*)&Bs[kk][tx * 8];
            float4 b1 = *(const float4*)&Bs[kk][tx * 8 + 4];
            float a[8] = {a0.x, a0.y, a0.z, a0.w, a1.x, a1.y, a1.z, a1.w};
            float b[8] = {b0.x, b0.y, b0.z, b0.w, b1.x, b1.y, b1.z, b1.w};
            #pragma unroll
            for (int i = 0; i < 8; i++)
                #pragma unroll
                for (int j = 0; j < 8; j++) acc[i][j] += a[i] * b[j];
        }
        __syncthreads();
    }
    #pragma unroll
    for (int i = 0; i < 8; i++) {
        int m = m0 + ty * 8 + i;
        if (m >= M) continue;
        #pragma unroll
        for (int j = 0; j < 8; j++) {
            int n = n0 + tx * 8 + j;
            if (n < N) C[(size_t)m * N + n] = acc[i][j];
        }
    }
}

// ---------------- scores: S[b,h,q,k] = ((q+u)·k + (q+v)·p[k-q+T-1]) * inv_sqrt(DK)
// Tile 64x64 per block, DK=128 reduced in chunks of 16.
__global__ void __launch_bounds__(256) scores_kernel(const float* __restrict__ q,
                                                     const float* __restrict__ k,
                                                     const float* __restrict__ p,
                                                     const float* __restrict__ bu,
                                                     const float* __restrict__ bv,
                                                     float* __restrict__ s) {
    int q0 = blockIdx.x * 64;
    int k0 = blockIdx.y * 64;
    int bh = blockIdx.z;
    int b = bh >> 3, h = bh & 7;

    __shared__ float qs[16][64];
    __shared__ float ks[16][64];
    __shared__ float ps[16][128];   // 127 rows used
    __shared__ float us[16], vs[16];

    int tid = threadIdx.x;
    int tx = tid & 15, ty = tid >> 4;

    const float* qptr = q + (size_t)b * T_ * D_ + h * DK_;
    const float* kptr = k + (size_t)b * T_ * D_ + h * DK_;
    const float* pptr = p + h * DK_;
    int pbase = k0 - q0 + (T_ - 1) - 63;   // global p-row for local band row 0 (>=0 always)

    float ac[4][4], bd[4][4];
    #pragma unroll
    for (int i = 0; i < 4; i++)
        #pragma unroll
        for (int j = 0; j < 4; j++) { ac[i][j] = 0.f; bd[i][j] = 0.f; }

    for (int kc = 0; kc < DK_; kc += 16) {
        // q/k tiles: 64 rows x 16 cols = 256 float4 -> one per thread
        {
            int r = tid >> 2, c4 = (tid & 3) << 2;
            float4 t = *(const float4*)&qptr[(size_t)(q0 + r) * D_ + kc + c4];
            qs[c4 + 0][r] = t.x; qs[c4 + 1][r] = t.y; qs[c4 + 2][r] = t.z; qs[c4 + 3][r] = t.w;
            t = *(const float4*)&kptr[(size_t)(k0 + r) * D_ + kc + c4];
            ks[c4 + 0][r] = t.x; ks[c4 + 1][r] = t.y; ks[c4 + 2][r] = t.z; ks[c4 + 3][r] = t.w;
        }
        // p band: 127 rows x 16 cols = 508 float4
        for (int i = tid; i < 508; i += 256) {
            int r = i >> 2, c4 = (i & 3) << 2;
            float4 t = *(const float4*)&pptr[(size_t)(pbase + r) * D_ + kc + c4];
            ps[c4 + 0][r] = t.x; ps[c4 + 1][r] = t.y; ps[c4 + 2][r] = t.z; ps[c4 + 3][r] = t.w;
        }
        if (tid < 16) {
            us[tid] = bu[h * DK_ + kc + tid];
            vs[tid] = bv[h * DK_ + kc + tid];
        }
        __syncthreads();

        int pb = 4 * (tx - ty) + 60;   // local band base for this thread (0..120)
        #pragma unroll
        for (int kk = 0; kk < 16; kk++) {
            float u = us[kk], w = vs[kk];
            float qa[4], qb[4], kv[4], pv[7];
            #pragma unroll
            for (int i = 0; i < 4; i++) {
                float t = qs[kk][ty * 4 + i];
                qa[i] = t + u; qb[i] = t + w;
            }
            #pragma unroll
            for (int j = 0; j < 4; j++) kv[j] = ks[kk][tx * 4 + j];
            #pragma unroll
            for (int d = 0; d < 7; d++) pv[d] = ps[kk][pb + d];
            #pragma unroll
            for (int i = 0; i < 4; i++)
                #pragma unroll
                for (int j = 0; j < 4; j++) {
                    ac[i][j] += qa[i] * kv[j];
                    bd[i][j] += qb[i] * pv[j - i + 3];
                }
        }
        __syncthreads();
    }

    const float scale = 0.08838834764831845f;   // 1/sqrt(128)
    float* sout = s + ((size_t)bh * T_ + q0) * T_ + k0;
    #pragma unroll
    for (int i = 0; i < 4; i++) {
        float4 r4 = make_float4((ac[i][0] + bd[i][0]) * scale,
                                (ac[i][1] + bd[i][1]) * scale,
                                (ac[i][2] + bd[i][2]) * scale,
                                (ac[i][3] + bd[i][3]) * scale);
        *(float4*)&sout[(size_t)(ty * 4 + i) * T_ + tx * 4] = r4;
    }
}

// ---------------- row softmax over T_=2048, one block per row ----------------
__global__ void __launch_bounds__(256) softmax_kernel(float* __restrict__ s) {
    float* sr = s + (size_t)blockIdx.x * T_;
    int tid = threadIdx.x;
    float vl[8];
    float m = -1e30f;
    #pragma unroll
    for (int i = 0; i < 8; i++) { vl[i] = sr[tid + (i << 8)]; m = fmaxf(m, vl[i]); }
    #pragma unroll
    for (int o = 16; o; o >>= 1) m = fmaxf(m, __shfl_xor_sync(0xffffffffu, m, o));
    __shared__ float rmax[8], rsum[8];
    if ((tid & 31) == 0) rmax[tid >> 5] = m;
    __syncthreads();
    if (tid == 0) {
        float mm = rmax[0];
        for (int i = 1; i < 8; i++) mm = fmaxf(mm, rmax[i]);
        rmax[0] = mm;
    }
    __syncthreads();
    m = rmax[0];
    float sum = 0.f;
    #pragma unroll
    for (int i = 0; i < 8; i++) { vl[i] = __expf(vl[i] - m); sum += vl[i]; }
    #pragma unroll
    for (int o = 16; o; o >>= 1) sum += __shfl_xor_sync(0xffffffffu, sum, o);
    if ((tid & 31) == 0) rsum[tid >> 5] = sum;
    __syncthreads();
    if (tid == 0) {
        float ss = rsum[0];
        for (int i = 1; i < 8; i++) ss += rsum[i];
        rsum[0] = ss;
    }
    __syncthreads();
    float inv = 1.0f / rsum[0];
    #pragma unroll
    for (int i = 0; i < 8; i++) sr[tid + (i << 8)] = vl[i] * inv;
}

// ---------------- AV: out[b,q,h,:] = sum_k attn[bh,q,k] * v[b,k,h,:] ----------------
// Tile 64 (q) x 128 (dk full), reduce T_ in chunks of 16.
__global__ void __launch_bounds__(256) av_kernel(const float* __restrict__ attn,
                                                 const float* __restrict__ v,
                                                 float* __restrict__ out) {
    int bh = blockIdx.y;
    int b = bh >> 3, h = bh & 7;
    int q0 = blockIdx.x * 64;
    const float* A = attn + (size_t)bh * T_ * T_;
    const float* V = v + (size_t)b * T_ * D_ + h * DK_;
    float* O = out + (size_t)b * T_ * D_ + h * DK_;

    __shared__ float As[16][64];
    __shared__ float Vs[16][128];
    int tid = threadIdx.x;
    int tx = tid & 31, ty = tid >> 5;

    float acc[8][4];
    #pragma unroll
    for (int i = 0; i < 8; i++)
        #pragma unroll
        for (int j = 0; j < 4; j++) acc[i][j] = 0.f;

    for (int k0 = 0; k0 < T_; k0 += 16) {
        {
            int r = tid >> 2, c4 = (tid & 3) << 2;
            float4 t = *(const float4*)&A[(size_t)(q0 + r) * T_ + k0 + c4];
            As[c4 + 0][r] = t.x; As[c4 + 1][r] = t.y; As[c4 + 2][r] = t.z; As[c4 + 3][r] = t.w;
        }
        #pragma unroll
        for (int it = 0; it < 2; it++) {
            int i = tid + it * 256;          // float4 index; 512 = 16x128/4
            int r = i >> 5, c4 = (i & 31) << 2;
            *(float4*)&Vs[r][c4] = *(const float4*)&V[(size_t)(k0 + r) * D_ + c4];
        }
        __syncthreads();
        #pragma unroll
        for (int kk = 0; kk < 16; kk++) {
            float4 vv = *(const float4*)&Vs[kk][tx << 2];
            float bvals[4] = {vv.x, vv.y, vv.z, vv.w};
            float a[8];
            #pragma unroll
            for (int i = 0; i < 8; i++) a[i] = As[kk][(ty << 3) + i];
            #pragma unroll
            for (int i = 0; i < 8; i++)
                #pragma unroll
                for (int j = 0; j < 4; j++) acc[i][j] += a[i] * bvals[j];
        }
        __syncthreads();
    }
    #pragma unroll
    for (int i = 0; i < 8; i++) {
        float4 r4 = make_float4(acc[i][0], acc[i][1], acc[i][2], acc[i][3]);
        *(float4*)&O[(size_t)(q0 + (ty << 3) + i) * D_ + (tx << 2)] = r4;
    }
}

// ---------------- launch ----------------
extern "C" void kernel_launch(void* const* d_in, const int* in_sizes, int n_in,
                              void* d_out, int out_size) {
    (void)in_sizes; (void)n_in; (void)out_size;
    const float* x  = (const float*)d_in[0];
    const float* pe = (const float*)d_in[1];
    const float* Wq = (const float*)d_in[2];
    const float* Wk = (const float*)d_in[3];
    const float* Wv = (const float*)d_in[4];
    const float* Wo = (const float*)d_in[5];
    const float* Wp = (const float*)d_in[6];
    const float* bu = (const float*)d_in[7];
    const float* bv = (const float*)d_in[8];

    float *q, *k, *v, *p, *s, *ao;
    cudaGetSymbolAddress((void**)&q,  g_q);
    cudaGetSymbolAddress((void**)&k,  g_k);
    cudaGetSymbolAddress((void**)&v,  g_v);
    cudaGetSymbolAddress((void**)&p,  g_p);
    cudaGetSymbolAddress((void**)&s,  g_s);
    cudaGetSymbolAddress((void**)&ao, g_ao);

    // projections
    gemm_nt<<<dim3(D_ / 128, BT_ / 128), 256>>>(x,  Wq, q,  BT_, D_, D_);
    gemm_nt<<<dim3(D_ / 128, BT_ / 128), 256>>>(x,  Wk, k,  BT_, D_, D_);
    gemm_nt<<<dim3(D_ / 128, BT_ / 128), 256>>>(x,  Wv, v,  BT_, D_, D_);
    gemm_nt<<<dim3(D_ / 128, (P_ + 127) / 128), 256>>>(pe, Wp, p, P_, D_, D_);

    // scores with fused rel-shift band
    scores_kernel<<<dim3(T_ / 64, T_ / 64, B_ * H_), 256>>>(q, k, p, bu, bv, s);

    // softmax
    softmax_kernel<<<B_ * H_ * T_, 256>>>(s);

    // attn @ v
    av_kernel<<<dim3(T_ / 64, B_ * H_), 256>>>(s, v, ao);

    // output projection
    gemm_nt<<<dim3(D_ / 128, BT_ / 128), 256>>>(ao, Wo, (float*)d_out, BT_, D_, D_);
}

// round 3
// speedup vs baseline: 1.1904x; 1.1904x over previous
#include <cuda_runtime.h>
#include <math.h>

#define B_  4
#define T_  2048
#define D_  1024
#define H_  8
#define DK_ 128
#define P_  (2*T_-1)
#define BT_ (B_*T_)

// ---------------- scratch (device globals: allocation-free) ----------------
static __device__ float g_q [(size_t)BT_ * D_];
static __device__ float g_k [(size_t)BT_ * D_];
static __device__ float g_v [(size_t)BT_ * D_];
static __device__ float g_p [(size_t)P_  * D_];
static __device__ float g_s [(size_t)B_ * H_ * T_ * T_];   // 512 MB scores/attn
static __device__ float g_ao[(size_t)BT_ * D_];

// ---------------- generic NT GEMM: C[M,N] = A[M,K] @ B[N,K]^T ----------------
// BM=BN=128, BK=8, 256 threads, 8x8 per thread.
__device__ __forceinline__ void gemm_nt_body(const float* __restrict__ A,
                                             const float* __restrict__ B,
                                             float* __restrict__ C,
                                             int M, int N, int K,
                                             int m0, int n0) {
    __shared__ float As[8][128];
    __shared__ float Bs[8][128];
    int tid = threadIdx.x;
    int tx = tid & 15, ty = tid >> 4;
    float acc[8][8];
    #pragma unroll
    for (int i = 0; i < 8; i++)
        #pragma unroll
        for (int j = 0; j < 8; j++) acc[i][j] = 0.f;

    int r  = tid >> 1;
    int c4 = (tid & 1) * 4;
    for (int k0 = 0; k0 < K; k0 += 8) {
        float4 av = make_float4(0.f, 0.f, 0.f, 0.f);
        float4 bv = make_float4(0.f, 0.f, 0.f, 0.f);
        int m = m0 + r, n = n0 + r;
        if (m < M) av = *(const float4*)&A[(size_t)m * K + k0 + c4];
        if (n < N) bv = *(const float4*)&B[(size_t)n * K + k0 + c4];
        As[c4 + 0][r] = av.x; As[c4 + 1][r] = av.y;
        As[c4 + 2][r] = av.z; As[c4 + 3][r] = av.w;
        Bs[c4 + 0][r] = bv.x; Bs[c4 + 1][r] = bv.y;
        Bs[c4 + 2][r] = bv.z; Bs[c4 + 3][r] = bv.w;
        __syncthreads();
        #pragma unroll
        for (int kk = 0; kk < 8; kk++) {
            float a[8], b[8];
            *(float4*)&a[0] = *(const float4*)&As[kk][ty * 8];
            *(float4*)&a[4] = *(const float4*)&As[kk][ty * 8 + 4];
            *(float4*)&b[0] = *(const float4*)&Bs[kk][tx * 8];
            *(float4*)&b[4] = *(const float4*)&Bs[kk][tx * 8 + 4];
            #pragma unroll
            for (int i = 0; i < 8; i++)
                #pragma unroll
                for (int j = 0; j < 8; j++) acc[i][j] += a[i] * b[j];
        }
        __syncthreads();
    }
    #pragma unroll
    for (int i = 0; i < 8; i++) {
        int m = m0 + ty * 8 + i;
        if (m >= M) continue;
        #pragma unroll
        for (int j = 0; j < 8; j++) {
            int n = n0 + tx * 8 + j;
            if (n < N) C[(size_t)m * N + n] = acc[i][j];
        }
    }
}

__global__ void __launch_bounds__(256) gemm_nt(const float* __restrict__ A,
                                               const float* __restrict__ B,
                                               float* __restrict__ C,
                                               int M, int N, int K) {
    gemm_nt_body(A, B, C, M, N, K, blockIdx.y * 128, blockIdx.x * 128);
}

// fused projections: z=0,1,2 -> x@{Wq,Wk,Wv}^T; z=3 -> pe@Wp^T (M=P_)
__global__ void __launch_bounds__(256) gemm_proj4(
        const float* __restrict__ x,  const float* __restrict__ pe,
        const float* __restrict__ Wq, const float* __restrict__ Wk,
        const float* __restrict__ Wv, const float* __restrict__ Wp,
        float* __restrict__ q, float* __restrict__ k,
        float* __restrict__ v, float* __restrict__ p) {
    int z = blockIdx.z;
    const float* A = (z == 3) ? pe : x;
    const float* B = (z == 0) ? Wq : (z == 1) ? Wk : (z == 2) ? Wv : Wp;
    float* C       = (z == 0) ? q  : (z == 1) ? k  : (z == 2) ? v  : p;
    int M          = (z == 3) ? P_ : BT_;
    int m0 = blockIdx.y * 128;
    if (m0 >= M) return;
    gemm_nt_body(A, B, C, M, D_, D_, m0, blockIdx.x * 128);
}

// ---------------- scores: S[b,h,q,k] = ((q+u)·k + (q+v)·p[k-q+T-1]) / sqrt(DK)
// 128x128 tile per block, 8x8 per thread, DK reduced in chunks of 16.
__global__ void __launch_bounds__(256, 2) scores_kernel(const float* __restrict__ q,
                                                        const float* __restrict__ k,
                                                        const float* __restrict__ p,
                                                        const float* __restrict__ bu,
                                                        const float* __restrict__ bv,
                                                        float* __restrict__ s) {
    int q0 = blockIdx.x * 128;
    int k0 = blockIdx.y * 128;
    int bh = blockIdx.z;
    int b = bh >> 3, h = bh & 7;

    __shared__ float qs[16][128];
    __shared__ float ks[16][128];
    __shared__ float ps[16][256];   // 255 band rows used
    __shared__ float us[16], vs[16];

    int tid = threadIdx.x;
    int tx = tid & 15, ty = tid >> 4;

    const float* qptr = q + (size_t)b * T_ * D_ + h * DK_;
    const float* kptr = k + (size_t)b * T_ * D_ + h * DK_;
    const float* pptr = p + h * DK_;
    int pbase = k0 - q0 + (T_ - 1) - 127;   // p-row for local band index 0 (always >=0)

    float acc[8][8];
    #pragma unroll
    for (int i = 0; i < 8; i++)
        #pragma unroll
        for (int j = 0; j < 8; j++) acc[i][j] = 0.f;

    for (int kc = 0; kc < DK_; kc += 16) {
        // q/k tiles: 128 rows x 16 cols = 512 float4 each -> 2 per thread
        #pragma unroll
        for (int it = 0; it < 2; it++) {
            int idx = tid + it * 256;
            int r = idx >> 2, c4 = (idx & 3) << 2;
            float4 t = *(const float4*)&qptr[(size_t)(q0 + r) * D_ + kc + c4];
            qs[c4 + 0][r] = t.x; qs[c4 + 1][r] = t.y; qs[c4 + 2][r] = t.z; qs[c4 + 3][r] = t.w;
            t = *(const float4*)&kptr[(size_t)(k0 + r) * D_ + kc + c4];
            ks[c4 + 0][r] = t.x; ks[c4 + 1][r] = t.y; ks[c4 + 2][r] = t.z; ks[c4 + 3][r] = t.w;
        }
        // p band: 255 rows x 16 cols = 1020 float4
        #pragma unroll
        for (int it = 0; it < 4; it++) {
            int idx = tid + it * 256;
            if (idx < 1020) {
                int r = idx >> 2, c4 = (idx & 3) << 2;
                float4 t = *(const float4*)&pptr[(size_t)(pbase + r) * D_ + kc + c4];
                ps[c4 + 0][r] = t.x; ps[c4 + 1][r] = t.y; ps[c4 + 2][r] = t.z; ps[c4 + 3][r] = t.w;
            }
        }
        if (tid < 16) {
            us[tid] = bu[h * DK_ + kc + tid];
            vs[tid] = bv[h * DK_ + kc + tid];
        }
        __syncthreads();

        int pbb = 8 * (tx - ty) + 120;   // 32B-aligned band base, 0..240
        #pragma unroll 4
        for (int kk = 0; kk < 16; kk++) {
            float u = us[kk], w = vs[kk];
            float kv[8], pv[16];
            *(float4*)&kv[0]  = *(const float4*)&ks[kk][tx * 8];
            *(float4*)&kv[4]  = *(const float4*)&ks[kk][tx * 8 + 4];
            *(float4*)&pv[0]  = *(const float4*)&ps[kk][pbb];
            *(float4*)&pv[4]  = *(const float4*)&ps[kk][pbb + 4];
            *(float4*)&pv[8]  = *(const float4*)&ps[kk][pbb + 8];
            *(float4*)&pv[12] = *(const float4*)&ps[kk][pbb + 12];
            #pragma unroll
            for (int i = 0; i < 8; i++) {
                float qv = qs[kk][ty * 8 + i];
                float qa = qv + u;
                float qb = qv + w;
                #pragma unroll
                for (int j = 0; j < 8; j++) acc[i][j] += qa * kv[j];
                #pragma unroll
                for (int j = 0; j < 8; j++) acc[i][j] += qb * pv[j - i + 7];
            }
        }
        __syncthreads();
    }

    const float scale = 0.08838834764831845f;   // 1/sqrt(128)
    float* sout = s + ((size_t)bh * T_ + q0) * T_ + k0;
    #pragma unroll
    for (int i = 0; i < 8; i++) {
        float* row = &sout[(size_t)(ty * 8 + i) * T_ + tx * 8];
        float4 r0 = make_float4(acc[i][0] * scale, acc[i][1] * scale,
                                acc[i][2] * scale, acc[i][3] * scale);
        float4 r1 = make_float4(acc[i][4] * scale, acc[i][5] * scale,
                                acc[i][6] * scale, acc[i][7] * scale);
        *(float4*)&row[0] = r0;
        *(float4*)&row[4] = r1;
    }
}

// ---------------- row softmax over T_=2048, one block per row ----------------
__global__ void __launch_bounds__(256) softmax_kernel(float* __restrict__ s) {
    float* sr = s + (size_t)blockIdx.x * T_;
    int tid = threadIdx.x;
    float vl[8];
    float m = -1e30f;
    #pragma unroll
    for (int i = 0; i < 8; i++) { vl[i] = sr[tid + (i << 8)]; m = fmaxf(m, vl[i]); }
    #pragma unroll
    for (int o = 16; o; o >>= 1) m = fmaxf(m, __shfl_xor_sync(0xffffffffu, m, o));
    __shared__ float rmax[8], rsum[8];
    if ((tid & 31) == 0) rmax[tid >> 5] = m;
    __syncthreads();
    if (tid == 0) {
        float mm = rmax[0];
        for (int i = 1; i < 8; i++) mm = fmaxf(mm, rmax[i]);
        rmax[0] = mm;
    }
    __syncthreads();
    m = rmax[0];
    float sum = 0.f;
    #pragma unroll
    for (int i = 0; i < 8; i++) { vl[i] = __expf(vl[i] - m); sum += vl[i]; }
    #pragma unroll
    for (int o = 16; o; o >>= 1) sum += __shfl_xor_sync(0xffffffffu, sum, o);
    if ((tid & 31) == 0) rsum[tid >> 5] = sum;
    __syncthreads();
    if (tid == 0) {
        float ss = rsum[0];
        for (int i = 1; i < 8; i++) ss += rsum[i];
        rsum[0] = ss;
    }
    __syncthreads();
    float inv = 1.0f / rsum[0];
    #pragma unroll
    for (int i = 0; i < 8; i++) sr[tid + (i << 8)] = vl[i] * inv;
}

// ---------------- AV: out[b,q,h,:] = sum_k attn[bh,q,k] * v[b,k,h,:] ----------------
// gemm-style 128(q) x 128(dk) tile, BK=8, 8x8 per thread.
__global__ void __launch_bounds__(256) av_kernel(const float* __restrict__ attn,
                                                 const float* __restrict__ v,
                                                 float* __restrict__ out) {
    int bh = blockIdx.z;
    int b = bh >> 3, h = bh & 7;
    int q0 = blockIdx.y * 128;
    const float* A = attn + (size_t)bh * T_ * T_;
    const float* V = v + (size_t)b * T_ * D_ + h * DK_;
    float* O = out + (size_t)b * T_ * D_ + h * DK_;

    __shared__ float As[8][128];
    __shared__ float Vs[8][128];
    int tid = threadIdx.x;
    int tx = tid & 15, ty = tid >> 4;

    float acc[8][8];
    #pragma unroll
    for (int i = 0; i < 8; i++)
        #pragma unroll
        for (int j = 0; j < 8; j++) acc[i][j] = 0.f;

    int ra = tid >> 1, ca = (tid & 1) * 4;
    int rv = tid >> 5, cv = (tid & 31) * 4;
    for (int k0 = 0; k0 < T_; k0 += 8) {
        float4 t = *(const float4*)&A[(size_t)(q0 + ra) * T_ + k0 + ca];
        As[ca + 0][ra] = t.x; As[ca + 1][ra] = t.y;
        As[ca + 2][ra] = t.z; As[ca + 3][ra] = t.w;
        *(float4*)&Vs[rv][cv] = *(const float4*)&V[(size_t)(k0 + rv) * D_ + cv];
        __syncthreads();
        #pragma unroll
        for (int kk = 0; kk < 8; kk++) {
            float a[8], bvals[8];
            *(float4*)&a[0]     = *(const float4*)&As[kk][ty * 8];
            *(float4*)&a[4]     = *(const float4*)&As[kk][ty * 8 + 4];
            *(float4*)&bvals[0] = *(const float4*)&Vs[kk][tx * 8];
            *(float4*)&bvals[4] = *(const float4*)&Vs[kk][tx * 8 + 4];
            #pragma unroll
            for (int i = 0; i < 8; i++)
                #pragma unroll
                for (int j = 0; j < 8; j++) acc[i][j] += a[i] * bvals[j];
        }
        __syncthreads();
    }
    #pragma unroll
    for (int i = 0; i < 8; i++) {
        float* row = &O[(size_t)(q0 + ty * 8 + i) * D_ + tx * 8];
        *(float4*)&row[0] = make_float4(acc[i][0], acc[i][1], acc[i][2], acc[i][3]);
        *(float4*)&row[4] = make_float4(acc[i][4], acc[i][5], acc[i][6], acc[i][7]);
    }
}

// ---------------- launch ----------------
extern "C" void kernel_launch(void* const* d_in, const int* in_sizes, int n_in,
                              void* d_out, int out_size) {
    (void)in_sizes; (void)n_in; (void)out_size;
    const float* x  = (const float*)d_in[0];
    const float* pe = (const float*)d_in[1];
    const float* Wq = (const float*)d_in[2];
    const float* Wk = (const float*)d_in[3];
    const float* Wv = (const float*)d_in[4];
    const float* Wo = (const float*)d_in[5];
    const float* Wp = (const float*)d_in[6];
    const float* bu = (const float*)d_in[7];
    const float* bv = (const float*)d_in[8];

    float *q, *k, *v, *p, *s, *ao;
    cudaGetSymbolAddress((void**)&q,  g_q);
    cudaGetSymbolAddress((void**)&k,  g_k);
    cudaGetSymbolAddress((void**)&v,  g_v);
    cudaGetSymbolAddress((void**)&p,  g_p);
    cudaGetSymbolAddress((void**)&s,  g_s);
    cudaGetSymbolAddress((void**)&ao, g_ao);

    // fused projections (q,k,v,p) in one launch
    gemm_proj4<<<dim3(D_ / 128, BT_ / 128, 4), 256>>>(x, pe, Wq, Wk, Wv, Wp, q, k, v, p);

    // scores with fused rel-shift band
    scores_kernel<<<dim3(T_ / 128, T_ / 128, B_ * H_), 256>>>(q, k, p, bu, bv, s);

    // softmax
    softmax_kernel<<<B_ * H_ * T_, 256>>>(s);

    // attn @ v
    av_kernel<<<dim3(1, T_ / 128, B_ * H_), 256>>>(s, v, ao);

    // output projection
    gemm_nt<<<dim3(D_ / 128, BT_ / 128), 256>>>(ao, Wo, (float*)d_out, BT_, D_, D_);
}

// round 6
// speedup vs baseline: 1.7452x; 1.4660x over previous
#include <cuda_runtime.h>
#include <cuda_bf16.h>
#include <stdint.h>
#include <math.h>

#define B_  4
#define T_  2048
#define D_  1024
#define H_  8
#define DK_ 128
#define P_  (2*T_-1)
#define BT_ (B_*T_)

// ---------------- scratch (device globals: allocation-free) ----------------
static __device__ float g_q [(size_t)BT_ * D_];
static __device__ float g_k [(size_t)BT_ * D_];
static __device__ float g_v [(size_t)BT_ * D_];
static __device__ float g_vt[(size_t)B_ * H_ * DK_ * T_];   // v transposed: [bh][dk][t]
static __device__ float g_p [(size_t)P_  * D_];
static __device__ float g_s [(size_t)B_ * H_ * T_ * T_];    // scores/attn
static __device__ float g_ao[(size_t)BT_ * D_];

// ============================ helpers ============================
__device__ __forceinline__ uint32_t smem_u32(const void* p) {
    uint32_t a;
    asm("{ .reg .u64 t; cvta.to.shared.u64 t, %1; cvt.u32.u64 %0, t; }" : "=r"(a) : "l"(p));
    return a;
}

__device__ __forceinline__ uint32_t pack_bf2(__nv_bfloat16 a, __nv_bfloat16 b) {
    return (uint32_t)__bfloat16_as_ushort(a) | ((uint32_t)__bfloat16_as_ushort(b) << 16);
}

// split float4 into bf16 hi (2x uint32) and lo (2x uint32)
__device__ __forceinline__ void cvt_hilo(float4 a, uint2& h, uint2& l) {
    __nv_bfloat16 h0 = __float2bfloat16_rn(a.x), h1 = __float2bfloat16_rn(a.y);
    __nv_bfloat16 h2 = __float2bfloat16_rn(a.z), h3 = __float2bfloat16_rn(a.w);
    __nv_bfloat16 l0 = __float2bfloat16_rn(a.x - __bfloat162float(h0));
    __nv_bfloat16 l1 = __float2bfloat16_rn(a.y - __bfloat162float(h1));
    __nv_bfloat16 l2 = __float2bfloat16_rn(a.z - __bfloat162float(h2));
    __nv_bfloat16 l3 = __float2bfloat16_rn(a.w - __bfloat162float(h3));
    h = make_uint2(pack_bf2(h0, h1), pack_bf2(h2, h3));
    l = make_uint2(pack_bf2(l0, l1), pack_bf2(l2, l3));
}

#define LDSM4(r0, r1, r2, r3, addr) \
    asm volatile("ldmatrix.sync.aligned.m8n8.x4.shared.b16 {%0,%1,%2,%3}, [%4];" \
        : "=r"(r0), "=r"(r1), "=r"(r2), "=r"(r3) : "r"(addr))

#define MMA16816(c, a, b0, b1) \
    asm volatile("mma.sync.aligned.m16n8k16.row.col.f32.bf16.bf16.f32 " \
        "{%0,%1,%2,%3}, {%4,%5,%6,%7}, {%8,%9}, {%0,%1,%2,%3};" \
        : "+f"((c)[0]), "+f"((c)[1]), "+f"((c)[2]), "+f"((c)[3]) \
        : "r"((a)[0]), "r"((a)[1]), "r"((a)[2]), "r"((a)[3]), "r"(b0), "r"(b1))

// ======== warp-MMA NT GEMM body: C[128,128] tile = A[m,:]·B[n,:] (bf16 hi/lo) ========
// 256 threads, 8 warps in 4(m) x 2(n); per warp 32x64; K multiple of 32.
#define LDSTRIDE 40   // uint16 elements per smem row (80B: conflict-free ldmatrix)
__device__ __forceinline__ void mm_body(const float* __restrict__ A, int lda,
                                        const float* __restrict__ B, int ldb,
                                        float* __restrict__ C, int ldc,
                                        int M, int K, int m0, int n0) {
    __shared__ __align__(16) uint16_t Ah[128][LDSTRIDE];
    __shared__ __align__(16) uint16_t Al[128][LDSTRIDE];
    __shared__ __align__(16) uint16_t Bh[128][LDSTRIDE];
    __shared__ __align__(16) uint16_t Bl[128][LDSTRIDE];

    int tid  = threadIdx.x;
    int lane = tid & 31, wid = tid >> 5;
    int wm = (wid & 3) * 32;        // warp row base in tile
    int wn = (wid >> 2) * 64;       // warp col base in tile
    int lr  = lane & 15;            // ldmatrix row supplier
    int lc8 = (lane >> 4) << 3;     // ldmatrix col group

    float acc[2][8][4];
    #pragma unroll
    for (int mt = 0; mt < 2; mt++)
        #pragma unroll
        for (int nt = 0; nt < 8; nt++)
            #pragma unroll
            for (int e = 0; e < 4; e++) acc[mt][nt][e] = 0.f;

    for (int kc = 0; kc < K; kc += 32) {
        // ---- stage: 128 rows x 32 k as bf16 hi/lo for A and B ----
        #pragma unroll
        for (int it = 0; it < 4; it++) {
            int idx = tid + (it << 8);      // 0..1023
            int row = idx >> 3;
            int c4  = (idx & 7) << 2;
            float4 av = (m0 + row < M)
                ? *(const float4*)&A[(size_t)(m0 + row) * lda + kc + c4]
                : make_float4(0.f, 0.f, 0.f, 0.f);
            float4 bv = *(const float4*)&B[(size_t)(n0 + row) * ldb + kc + c4];
            uint2 h, l;
            cvt_hilo(av, h, l);
            *(uint2*)&Ah[row][c4] = h;
            *(uint2*)&Al[row][c4] = l;
            cvt_hilo(bv, h, l);
            *(uint2*)&Bh[row][c4] = h;
            *(uint2*)&Bl[row][c4] = l;
        }
        __syncthreads();

        // ---- compute: 3 passes (AhBh, AhBl, AlBh) ----
        #pragma unroll
        for (int pass = 0; pass < 3; pass++) {
            const uint16_t (*pa)[LDSTRIDE] = (pass == 2) ? Al : Ah;
            const uint16_t (*pb)[LDSTRIDE] = (pass == 1) ? Bl : Bh;
            #pragma unroll
            for (int kk = 0; kk < 32; kk += 16) {
                uint32_t afr[2][4];
                #pragma unroll
                for (int mt = 0; mt < 2; mt++) {
                    uint32_t ad = smem_u32(&pa[wm + mt * 16 + lr][kk + lc8]);
                    LDSM4(afr[mt][0], afr[mt][1], afr[mt][2], afr[mt][3], ad);
                }
                #pragma unroll
                for (int g = 0; g < 4; g++) {
                    uint32_t b0, b1, b2, b3;
                    uint32_t bd = smem_u32(&pb[wn + g * 16 + lr][kk + lc8]);
                    LDSM4(b0, b1, b2, b3, bd);
                    #pragma unroll
                    for (int mt = 0; mt < 2; mt++) {
                        MMA16816(acc[mt][2 * g],     afr[mt], b0, b2);
                        MMA16816(acc[mt][2 * g + 1], afr[mt], b1, b3);
                    }
                }
            }
        }
        __syncthreads();
    }

    // ---- epilogue: write acc to C ----
    int g  = lane >> 2;
    int tg = lane & 3;
    #pragma unroll
    for (int mt = 0; mt < 2; mt++) {
        int r0 = m0 + wm + mt * 16 + g;
        int r1 = r0 + 8;
        #pragma unroll
        for (int nt = 0; nt < 8; nt++) {
            int col = n0 + wn + nt * 8 + tg * 2;
            if (r0 < M) *(float2*)&C[(size_t)r0 * ldc + col] = make_float2(acc[mt][nt][0], acc[mt][nt][1]);
            if (r1 < M) *(float2*)&C[(size_t)r1 * ldc + col] = make_float2(acc[mt][nt][2], acc[mt][nt][3]);
        }
    }
}

// ---------------- wrappers ----------------
__global__ void __launch_bounds__(256, 2) mm_proj(
        const float* __restrict__ x,  const float* __restrict__ pe,
        const float* __restrict__ Wq, const float* __restrict__ Wk,
        const float* __restrict__ Wv, const float* __restrict__ Wp,
        float* __restrict__ q, float* __restrict__ k,
        float* __restrict__ v, float* __restrict__ p) {
    int z = blockIdx.z;
    const float* A  = (z == 3) ? pe : x;
    const float* Bm = (z == 0) ? Wq : (z == 1) ? Wk : (z == 2) ? Wv : Wp;
    float* C        = (z == 0) ? q  : (z == 1) ? k  : (z == 2) ? v  : p;
    int M           = (z == 3) ? P_ : BT_;
    int m0 = blockIdx.y * 128;
    if (m0 >= M) return;
    mm_body(A, D_, Bm, D_, C, D_, M, D_, m0, blockIdx.x * 128);
}

__global__ void __launch_bounds__(256, 2) mm_av(const float* __restrict__ s,
                                                const float* __restrict__ vt,
                                                float* __restrict__ ao) {
    int bh = blockIdx.z;
    int b = bh >> 3, h = bh & 7;
    mm_body(s + (size_t)bh * T_ * T_, T_,
            vt + (size_t)bh * DK_ * T_, T_,
            ao + (size_t)b * T_ * D_ + h * DK_, D_,
            T_, T_, blockIdx.y * 128, 0);
}

__global__ void __launch_bounds__(256, 2) mm_out(const float* __restrict__ ao,
                                                 const float* __restrict__ Wo,
                                                 float* __restrict__ out) {
    mm_body(ao, D_, Wo, D_, out, D_, BT_, D_, blockIdx.y * 128, blockIdx.x * 128);
}

// ---------------- v transpose: vt[bh][dk][t] = v[b][t][h*DK+dk] ----------------
__global__ void __launch_bounds__(256) vtrans(const float* __restrict__ v,
                                              float* __restrict__ vt) {
    __shared__ float tile[32][33];
    int bh = blockIdx.z, b = bh >> 3, h = bh & 7;
    int t0 = blockIdx.x * 32, d0 = blockIdx.y * 32;
    int tx = threadIdx.x & 31, ty = threadIdx.x >> 5;
    #pragma unroll
    for (int i = 0; i < 4; ++i) {
        int t = t0 + ty + i * 8;
        tile[ty + i * 8][tx] = v[(size_t)(b * T_ + t) * D_ + h * DK_ + d0 + tx];
    }
    __syncthreads();
    #pragma unroll
    for (int i = 0; i < 4; ++i) {
        int dk = d0 + ty + i * 8;
        vt[((size_t)bh * DK_ + dk) * T_ + t0 + tx] = tile[tx][ty + i * 8];
    }
}

// ---------------- scores: S[b,h,q,k] = ((q+u)·k + (q+v)·p[k-q+T-1]) / sqrt(DK)
__global__ void __launch_bounds__(256, 2) scores_kernel(const float* __restrict__ q,
                                                        const float* __restrict__ k,
                                                        const float* __restrict__ p,
                                                        const float* __restrict__ bu,
                                                        const float* __restrict__ bv,
                                                        float* __restrict__ s) {
    int q0 = blockIdx.x * 128;
    int k0 = blockIdx.y * 128;
    int bh = blockIdx.z;
    int b = bh >> 3, h = bh & 7;

    __shared__ float qs[16][128];
    __shared__ float ks[16][128];
    __shared__ float ps[16][256];
    __shared__ float us[16], vs[16];

    int tid = threadIdx.x;
    int tx = tid & 15, ty = tid >> 4;

    const float* qptr = q + (size_t)b * T_ * D_ + h * DK_;
    const float* kptr = k + (size_t)b * T_ * D_ + h * DK_;
    const float* pptr = p + h * DK_;
    int pbase = k0 - q0 + (T_ - 1) - 127;

    float acc[8][8];
    #pragma unroll
    for (int i = 0; i < 8; i++)
        #pragma unroll
        for (int j = 0; j < 8; j++) acc[i][j] = 0.f;

    for (int kc = 0; kc < DK_; kc += 16) {
        #pragma unroll
        for (int it = 0; it < 2; it++) {
            int idx = tid + it * 256;
            int r = idx >> 2, c4 = (idx & 3) << 2;
            float4 t = *(const float4*)&qptr[(size_t)(q0 + r) * D_ + kc + c4];
            qs[c4 + 0][r] = t.x; qs[c4 + 1][r] = t.y; qs[c4 + 2][r] = t.z; qs[c4 + 3][r] = t.w;
            t = *(const float4*)&kptr[(size_t)(k0 + r) * D_ + kc + c4];
            ks[c4 + 0][r] = t.x; ks[c4 + 1][r] = t.y; ks[c4 + 2][r] = t.z; ks[c4 + 3][r] = t.w;
        }
        #pragma unroll
        for (int it = 0; it < 4; it++) {
            int idx = tid + it * 256;
            if (idx < 1020) {
                int r = idx >> 2, c4 = (idx & 3) << 2;
                float4 t = *(const float4*)&pptr[(size_t)(pbase + r) * D_ + kc + c4];
                ps[c4 + 0][r] = t.x; ps[c4 + 1][r] = t.y; ps[c4 + 2][r] = t.z; ps[c4 + 3][r] = t.w;
            }
        }
        if (tid < 16) {
            us[tid] = bu[h * DK_ + kc + tid];
            vs[tid] = bv[h * DK_ + kc + tid];
        }
        __syncthreads();

        int pbb = 8 * (tx - ty) + 120;
        #pragma unroll 4
        for (int kk = 0; kk < 16; kk++) {
            float u = us[kk], w = vs[kk];
            float kv[8], pv[16];
            *(float4*)&kv[0]  = *(const float4*)&ks[kk][tx * 8];
            *(float4*)&kv[4]  = *(const float4*)&ks[kk][tx * 8 + 4];
            *(float4*)&pv[0]  = *(const float4*)&ps[kk][pbb];
            *(float4*)&pv[4]  = *(const float4*)&ps[kk][pbb + 4];
            *(float4*)&pv[8]  = *(const float4*)&ps[kk][pbb + 8];
            *(float4*)&pv[12] = *(const float4*)&ps[kk][pbb + 12];
            #pragma unroll
            for (int i = 0; i < 8; i++) {
                float qv = qs[kk][ty * 8 + i];
                float qa = qv + u;
                float qb = qv + w;
                #pragma unroll
                for (int j = 0; j < 8; j++) acc[i][j] += qa * kv[j];
                #pragma unroll
                for (int j = 0; j < 8; j++) acc[i][j] += qb * pv[j - i + 7];
            }
        }
        __syncthreads();
    }

    const float scale = 0.08838834764831845f;
    float* sout = s + ((size_t)bh * T_ + q0) * T_ + k0;
    #pragma unroll
    for (int i = 0; i < 8; i++) {
        float* row = &sout[(size_t)(ty * 8 + i) * T_ + tx * 8];
        *(float4*)&row[0] = make_float4(acc[i][0] * scale, acc[i][1] * scale,
                                        acc[i][2] * scale, acc[i][3] * scale);
        *(float4*)&row[4] = make_float4(acc[i][4] * scale, acc[i][5] * scale,
                                        acc[i][6] * scale, acc[i][7] * scale);
    }
}

// ---------------- row softmax over T_=2048 ----------------
__global__ void __launch_bounds__(256) softmax_kernel(float* __restrict__ s) {
    float* sr = s + (size_t)blockIdx.x * T_;
    int tid = threadIdx.x;
    float vl[8];
    float m = -1e30f;
    #pragma unroll
    for (int i = 0; i < 8; i++) { vl[i] = sr[tid + (i << 8)]; m = fmaxf(m, vl[i]); }
    #pragma unroll
    for (int o = 16; o; o >>= 1) m = fmaxf(m, __shfl_xor_sync(0xffffffffu, m, o));
    __shared__ float rmax[8], rsum[8];
    if ((tid & 31) == 0) rmax[tid >> 5] = m;
    __syncthreads();
    if (tid == 0) {
        float mm = rmax[0];
        for (int i = 1; i < 8; i++) mm = fmaxf(mm, rmax[i]);
        rmax[0] = mm;
    }
    __syncthreads();
    m = rmax[0];
    float sum = 0.f;
    #pragma unroll
    for (int i = 0; i < 8; i++) { vl[i] = __expf(vl[i] - m); sum += vl[i]; }
    #pragma unroll
    for (int o = 16; o; o >>= 1) sum += __shfl_xor_sync(0xffffffffu, sum, o);
    if ((tid & 31) == 0) rsum[tid >> 5] = sum;
    __syncthreads();
    if (tid == 0) {
        float ss = rsum[0];
        for (int i = 1; i < 8; i++) ss += rsum[i];
        rsum[0] = ss;
    }
    __syncthreads();
    float inv = 1.0f / rsum[0];
    #pragma unroll
    for (int i = 0; i < 8; i++) sr[tid + (i << 8)] = vl[i] * inv;
}

// ---------------- launch ----------------
extern "C" void kernel_launch(void* const* d_in, const int* in_sizes, int n_in,
                              void* d_out, int out_size) {
    (void)in_sizes; (void)n_in; (void)out_size;
    const float* x  = (const float*)d_in[0];
    const float* pe = (const float*)d_in[1];
    const float* Wq = (const float*)d_in[2];
    const float* Wk = (const float*)d_in[3];
    const float* Wv = (const float*)d_in[4];
    const float* Wo = (const float*)d_in[5];
    const float* Wp = (const float*)d_in[6];
    const float* bu = (const float*)d_in[7];
    const float* bv = (const float*)d_in[8];

    float *q, *k, *v, *vt, *p, *s, *ao;
    cudaGetSymbolAddress((void**)&q,  g_q);
    cudaGetSymbolAddress((void**)&k,  g_k);
    cudaGetSymbolAddress((void**)&v,  g_v);
    cudaGetSymbolAddress((void**)&vt, g_vt);
    cudaGetSymbolAddress((void**)&p,  g_p);
    cudaGetSymbolAddress((void**)&s,  g_s);
    cudaGetSymbolAddress((void**)&ao, g_ao);

    // projections (q,k,v,p) on tensor cores (warp MMA, bf16 hi/lo split)
    mm_proj<<<dim3(D_ / 128, BT_ / 128, 4), 256>>>(x, pe, Wq, Wk, Wv, Wp, q, k, v, p);

    // transpose v for AV's B operand
    vtrans<<<dim3(T_ / 32, DK_ / 32, B_ * H_), 256>>>(v, vt);

    // scores with fused rel-shift band (fp32 FFMA)
    scores_kernel<<<dim3(T_ / 128, T_ / 128, B_ * H_), 256>>>(q, k, p, bu, bv, s);

    // softmax
    softmax_kernel<<<B_ * H_ * T_, 256>>>(s);

    // attn @ v on tensor cores
    mm_av<<<dim3(1, T_ / 128, B_ * H_), 256>>>(s, vt, ao);

    // output projection on tensor cores
    mm_out<<<dim3(D_ / 128, BT_ / 128, 1), 256>>>(ao, Wo, (float*)d_out);
}

// round 9
// speedup vs baseline: 1.8944x; 1.0855x over previous
#include <cuda_runtime.h>
#include <cuda_bf16.h>
#include <stdint.h>
#include <math.h>

#define B_  4
#define T_  2048
#define D_  1024
#define H_  8
#define DK_ 128
#define P_  (2*T_-1)
#define BT_ (B_*T_)

typedef __nv_bfloat16 bf16;

// ---------------- scratch (device globals: allocation-free) ----------------
static __device__ __align__(16) bf16 g_xh [(size_t)BT_ * D_];
static __device__ __align__(16) bf16 g_xl [(size_t)BT_ * D_];
static __device__ __align__(16) bf16 g_peh[(size_t)P_ * D_];
static __device__ __align__(16) bf16 g_pel[(size_t)P_ * D_];
static __device__ __align__(16) bf16 g_wqh[(size_t)D_ * D_], g_wql[(size_t)D_ * D_];
static __device__ __align__(16) bf16 g_wkh[(size_t)D_ * D_], g_wkl[(size_t)D_ * D_];
static __device__ __align__(16) bf16 g_wvh[(size_t)D_ * D_], g_wvl[(size_t)D_ * D_];
static __device__ __align__(16) bf16 g_woh[(size_t)D_ * D_], g_wol[(size_t)D_ * D_];
static __device__ __align__(16) bf16 g_wph[(size_t)D_ * D_], g_wpl[(size_t)D_ * D_];
static __device__ __align__(16) bf16 g_quh[(size_t)BT_ * D_], g_qul[(size_t)BT_ * D_];
static __device__ __align__(16) bf16 g_qvh[(size_t)BT_ * D_], g_qvl[(size_t)BT_ * D_];
static __device__ __align__(16) bf16 g_kh [(size_t)BT_ * D_], g_kl [(size_t)BT_ * D_];
static __device__ __align__(16) bf16 g_ph [(size_t)P_ * D_],  g_pl [(size_t)P_ * D_];
static __device__ __align__(16) float g_v [(size_t)BT_ * D_];
static __device__ __align__(16) bf16 g_vth[(size_t)B_ * H_ * DK_ * T_];
static __device__ __align__(16) bf16 g_vtl[(size_t)B_ * H_ * DK_ * T_];
static __device__ __align__(16) float g_s [(size_t)B_ * H_ * T_ * T_];
static __device__ __align__(16) bf16 g_ath[(size_t)B_ * H_ * T_ * T_];
static __device__ __align__(16) bf16 g_atl[(size_t)B_ * H_ * T_ * T_];
static __device__ __align__(16) bf16 g_aoh[(size_t)BT_ * D_], g_aol[(size_t)BT_ * D_];

// ============================ helpers ============================
__device__ __forceinline__ uint32_t smem_u32(const void* p) {
    uint32_t a;
    asm("{ .reg .u64 t; cvta.to.shared.u64 t, %1; cvt.u32.u64 %0, t; }" : "=r"(a) : "l"(p));
    return a;
}

__device__ __forceinline__ void split2(float a, float b, __nv_bfloat162& h, __nv_bfloat162& l) {
    bf16 ha = __float2bfloat16_rn(a), hb = __float2bfloat16_rn(b);
    h = __halves2bfloat162(ha, hb);
    l = __halves2bfloat162(__float2bfloat16_rn(a - __bfloat162float(ha)),
                           __float2bfloat16_rn(b - __bfloat162float(hb)));
}

#define LDSM4(r0, r1, r2, r3, addr) \
    asm volatile("ldmatrix.sync.aligned.m8n8.x4.shared.b16 {%0,%1,%2,%3}, [%4];" \
        : "=r"(r0), "=r"(r1), "=r"(r2), "=r"(r3) : "r"(addr))

#define MMA16816(c, a, b0, b1) \
    asm volatile("mma.sync.aligned.m16n8k16.row.col.f32.bf16.bf16.f32 " \
        "{%0,%1,%2,%3}, {%4,%5,%6,%7}, {%8,%9}, {%0,%1,%2,%3};" \
        : "+f"((c)[0]), "+f"((c)[1]), "+f"((c)[2]), "+f"((c)[3]) \
        : "r"((a)[0]), "r"((a)[1]), "r"((a)[2]), "r"((a)[3]), "r"(b0), "r"(b1))

// ---------------- split fp32 -> bf16 hi/lo ----------------
__global__ void __launch_bounds__(256) splitk(const float* __restrict__ s,
                                              bf16* __restrict__ h, bf16* __restrict__ l,
                                              int n) {
    int i = (blockIdx.x * 256 + threadIdx.x) * 4;
    if (i >= n) return;
    float4 v = *(const float4*)&s[i];
    __nv_bfloat162 h0, l0, h1, l1;
    split2(v.x, v.y, h0, l0);
    split2(v.z, v.w, h1, l1);
    *(__nv_bfloat162*)&h[i]     = h0;
    *(__nv_bfloat162*)&h[i + 2] = h1;
    *(__nv_bfloat162*)&l[i]     = l0;
    *(__nv_bfloat162*)&l[i + 2] = l1;
}

// ======== warp-MMA NT GEMM body: 128x128 tile, pre-split bf16 hi/lo, 3 passes ========
// 256 threads, 8 warps 4(m)x2(n), warp tile 32x64, K chunk 64.
#define LDST 72
#define SMEMSZ (4 * 128 * LDST * 2)
__device__ __forceinline__ void mm3_body(
        const bf16* __restrict__ Ah, const bf16* __restrict__ Al, int lda, int m0, int Mrows,
        const bf16* __restrict__ Bh, const bf16* __restrict__ Bl, int ldb, int n0, int Nrows,
        int K, float acc[2][8][4]) {
    extern __shared__ char dsm[];
    uint16_t (*sAh)[LDST] = (uint16_t(*)[LDST])(dsm);
    uint16_t (*sAl)[LDST] = (uint16_t(*)[LDST])(dsm + 18432);
    uint16_t (*sBh)[LDST] = (uint16_t(*)[LDST])(dsm + 36864);
    uint16_t (*sBl)[LDST] = (uint16_t(*)[LDST])(dsm + 55296);

    int tid = threadIdx.x, lane = tid & 31, wid = tid >> 5;
    int wm = (wid & 3) * 32, wn = (wid >> 2) * 64;
    int lr = lane & 15, lc8 = (lane >> 4) << 3;

    #pragma unroll
    for (int mt = 0; mt < 2; mt++)
        #pragma unroll
        for (int nt = 0; nt < 8; nt++)
            #pragma unroll
            for (int e = 0; e < 4; e++) acc[mt][nt][e] = 0.f;

    const uint4 z4 = make_uint4(0, 0, 0, 0);
    for (int kc = 0; kc < K; kc += 64) {
        #pragma unroll
        for (int it = 0; it < 4; it++) {
            int idx = tid + (it << 8);
            int row = idx >> 3, c8 = (idx & 7) << 3;
            int ar = m0 + row, br = n0 + row;
            size_t ao = (size_t)ar * lda + kc + c8;
            size_t bo = (size_t)br * ldb + kc + c8;
            uint4 vah = (ar < Mrows) ? *(const uint4*)(Ah + ao) : z4;
            uint4 val = (ar < Mrows) ? *(const uint4*)(Al + ao) : z4;
            uint4 vbh = (br < Nrows) ? *(const uint4*)(Bh + bo) : z4;
            uint4 vbl = (br < Nrows) ? *(const uint4*)(Bl + bo) : z4;
            *(uint4*)&sAh[row][c8] = vah;
            *(uint4*)&sAl[row][c8] = val;
            *(uint4*)&sBh[row][c8] = vbh;
            *(uint4*)&sBl[row][c8] = vbl;
        }
        __syncthreads();
        #pragma unroll
        for (int pass = 0; pass < 3; pass++) {
            const uint16_t (*pa)[LDST] = (pass == 2) ? sAl : sAh;
            const uint16_t (*pb)[LDST] = (pass == 1) ? sBl : sBh;
            #pragma unroll
            for (int kk = 0; kk < 64; kk += 16) {
                uint32_t afr[2][4];
                #pragma unroll
                for (int mt = 0; mt < 2; mt++) {
                    uint32_t ad = smem_u32(&pa[wm + mt * 16 + lr][kk + lc8]);
                    LDSM4(afr[mt][0], afr[mt][1], afr[mt][2], afr[mt][3], ad);
                }
                #pragma unroll
                for (int g = 0; g < 4; g++) {
                    uint32_t b0, b1, b2, b3;
                    uint32_t bd = smem_u32(&pb[wn + g * 16 + lr][kk + lc8]);
                    LDSM4(b0, b1, b2, b3, bd);
                    #pragma unroll
                    for (int mt = 0; mt < 2; mt++) {
                        MMA16816(acc[mt][2 * g],     afr[mt], b0, b2);
                        MMA16816(acc[mt][2 * g + 1], afr[mt], b1, b3);
                    }
                }
            }
        }
        __syncthreads();
    }
}

// iterate accumulator as float2 pairs: rl/cl local row/col, v0/v1 values
#define ACC_PAIRS(...) do {                                                   \
    int lane = threadIdx.x & 31, wid = threadIdx.x >> 5;                      \
    int wm = (wid & 3) * 32, wn = (wid >> 2) * 64;                            \
    int g = lane >> 2, tg = lane & 3;                                         \
    _Pragma("unroll") for (int mt = 0; mt < 2; mt++)                          \
    _Pragma("unroll") for (int hf = 0; hf < 2; hf++) {                        \
        int rl = wm + mt * 16 + g + hf * 8;                                   \
        _Pragma("unroll") for (int nt = 0; nt < 8; nt++) {                    \
            int cl = wn + nt * 8 + tg * 2;                                    \
            float v0 = acc[mt][nt][hf * 2], v1 = acc[mt][nt][hf * 2 + 1];     \
            { __VA_ARGS__ }                                                   \
        }                                                                     \
    }                                                                         \
} while (0)

// ---------------- projections: z=0 q(+biases), 1 k, 2 v, 3 p ----------------
__global__ void __launch_bounds__(256, 2) mm_proj(
        const bf16* xh, const bf16* xl, const bf16* peh, const bf16* pel,
        const bf16* wqh, const bf16* wql, const bf16* wkh, const bf16* wkl,
        const bf16* wvh, const bf16* wvl, const bf16* wph, const bf16* wpl,
        const float* bu, const float* bv,
        bf16* quh, bf16* qul, bf16* qvh, bf16* qvl,
        bf16* kh, bf16* kl, float* v, bf16* ph, bf16* pl) {
    int z = blockIdx.z;
    const bf16* Ah = (z == 3) ? peh : xh;
    const bf16* Al = (z == 3) ? pel : xl;
    const bf16* Bh = (z == 0) ? wqh : (z == 1) ? wkh : (z == 2) ? wvh : wph;
    const bf16* Bl = (z == 0) ? wql : (z == 1) ? wkl : (z == 2) ? wvl : wpl;
    int M = (z == 3) ? P_ : BT_;
    int m0 = blockIdx.y * 128;
    if (m0 >= M) return;
    int n0 = blockIdx.x * 128;
    float acc[2][8][4];
    mm3_body(Ah, Al, D_, m0, M, Bh, Bl, D_, n0, D_, D_, acc);

    if (z == 0) {
        ACC_PAIRS(
            int r = m0 + rl, c = n0 + cl;
            size_t idx = (size_t)r * D_ + c;
            __nv_bfloat162 h, l;
            split2(v0 + __ldg(&bu[c]), v1 + __ldg(&bu[c + 1]), h, l);
            *(__nv_bfloat162*)&quh[idx] = h; *(__nv_bfloat162*)&qul[idx] = l;
            split2(v0 + __ldg(&bv[c]), v1 + __ldg(&bv[c + 1]), h, l);
            *(__nv_bfloat162*)&qvh[idx] = h; *(__nv_bfloat162*)&qvl[idx] = l;
        );
    } else if (z == 1) {
        ACC_PAIRS(
            size_t idx = (size_t)(m0 + rl) * D_ + n0 + cl;
            __nv_bfloat162 h, l;
            split2(v0, v1, h, l);
            *(__nv_bfloat162*)&kh[idx] = h; *(__nv_bfloat162*)&kl[idx] = l;
        );
    } else if (z == 2) {
        ACC_PAIRS(
            *(float2*)&v[(size_t)(m0 + rl) * D_ + n0 + cl] = make_float2(v0, v1);
        );
    } else {
        ACC_PAIRS(
            int r = m0 + rl;
            if (r < P_) {
                size_t idx = (size_t)r * D_ + n0 + cl;
                __nv_bfloat162 h, l;
                split2(v0, v1, h, l);
                *(__nv_bfloat162*)&ph[idx] = h; *(__nv_bfloat162*)&pl[idx] = l;
            }
        );
    }
}

// ---------------- scores AC: S = (q+u)·k^T * scale ----------------
__global__ void __launch_bounds__(256, 2) scores_ac(const bf16* quh, const bf16* qul,
                                                    const bf16* kh, const bf16* kl,
                                                    float* __restrict__ s) {
    int bh = blockIdx.z, b = bh >> 3, h = bh & 7;
    size_t base = (size_t)b * T_ * D_ + h * DK_;
    int m0 = blockIdx.y * 128, n0 = blockIdx.x * 128;
    float acc[2][8][4];
    mm3_body(quh + base, qul + base, D_, m0, T_, kh + base, kl + base, D_, n0, T_, DK_, acc);
    const float scale = 0.08838834764831845f;
    float* sout = s + (size_t)bh * T_ * T_;
    ACC_PAIRS(
        *(float2*)&sout[(size_t)(m0 + rl) * T_ + n0 + cl] =
            make_float2(v0 * scale, v1 * scale);
    );
}

// ---------------- scores BD (diagonal GEMM): S[q][j+q-(T-1)] += (q+v)·p[j] * scale
__global__ void __launch_bounds__(256, 2) scores_bd(const bf16* qvh, const bf16* qvl,
                                                    const bf16* ph, const bf16* pl,
                                                    float* __restrict__ s) {
    int bh = blockIdx.z, b = bh >> 3, h = bh & 7;
    int qi = blockIdx.y;
    int j0 = (15 - qi + (int)blockIdx.x) * 128;
    size_t abase = (size_t)b * T_ * D_ + h * DK_;
    int m0 = qi * 128;
    float acc[2][8][4];
    mm3_body(qvh + abase, qvl + abase, D_, m0, T_,
             ph + h * DK_, pl + h * DK_, D_, j0, P_, DK_, acc);
    const float scale = 0.08838834764831845f;
    float* sout = s + (size_t)bh * T_ * T_;
    ACC_PAIRS(
        int q = m0 + rl;
        int k = j0 + cl + q - (T_ - 1);
        float* row = &sout[(size_t)q * T_];
        if ((unsigned)k < (unsigned)T_)       row[k]     += v0 * scale;
        if ((unsigned)(k + 1) < (unsigned)T_) row[k + 1] += v1 * scale;
    );
}

// ---------------- v transpose + split: vt[bh][dk][t] ----------------
__global__ void __launch_bounds__(256) vtrans(const float* __restrict__ v,
                                              bf16* __restrict__ vth,
                                              bf16* __restrict__ vtl) {
    __shared__ float tile[32][33];
    int bh = blockIdx.z, b = bh >> 3, h = bh & 7;
    int t0 = blockIdx.x * 32, d0 = blockIdx.y * 32;
    int tx = threadIdx.x & 31, ty = threadIdx.x >> 5;
    #pragma unroll
    for (int i = 0; i < 4; ++i) {
        int t = t0 + ty + i * 8;
        tile[ty + i * 8][tx] = v[(size_t)(b * T_ + t) * D_ + h * DK_ + d0 + tx];
    }
    __syncthreads();
    #pragma unroll
    for (int i = 0; i < 4; ++i) {
        int dk = d0 + ty + i * 8;
        float val = tile[tx][ty + i * 8];
        bf16 hv = __float2bfloat16_rn(val);
        size_t idx = ((size_t)bh * DK_ + dk) * T_ + t0 + tx;
        vth[idx] = hv;
        vtl[idx] = __float2bfloat16_rn(val - __bfloat162float(hv));
    }
}

// ---------------- softmax: fp32 scores -> bf16 hi/lo attn ----------------
__global__ void __launch_bounds__(256) softmax_kernel(const float* __restrict__ s,
                                                      bf16* __restrict__ ah,
                                                      bf16* __restrict__ al) {
    const float* sr = s + (size_t)blockIdx.x * T_;
    bf16* ahr = ah + (size_t)blockIdx.x * T_;
    bf16* alr = al + (size_t)blockIdx.x * T_;
    int tid = threadIdx.x;
    float vl[8];
    float m = -1e30f;
    #pragma unroll
    for (int i = 0; i < 8; i++) { vl[i] = sr[tid + (i << 8)]; m = fmaxf(m, vl[i]); }
    #pragma unroll
    for (int o = 16; o; o >>= 1) m = fmaxf(m, __shfl_xor_sync(0xffffffffu, m, o));
    __shared__ float rmax[8], rsum[8];
    if ((tid & 31) == 0) rmax[tid >> 5] = m;
    __syncthreads();
    if (tid == 0) {
        float mm = rmax[0];
        for (int i = 1; i < 8; i++) mm = fmaxf(mm, rmax[i]);
        rmax[0] = mm;
    }
    __syncthreads();
    m = rmax[0];
    float sum = 0.f;
    #pragma unroll
    for (int i = 0; i < 8; i++) { vl[i] = __expf(vl[i] - m); sum += vl[i]; }
    #pragma unroll
    for (int o = 16; o; o >>= 1) sum += __shfl_xor_sync(0xffffffffu, sum, o);
    if ((tid & 31) == 0) rsum[tid >> 5] = sum;
    __syncthreads();
    if (tid == 0) {
        float ss = rsum[0];
        for (int i = 1; i < 8; i++) ss += rsum[i];
        rsum[0] = ss;
    }
    __syncthreads();
    float inv = 1.0f / rsum[0];
    #pragma unroll
    for (int i = 0; i < 8; i++) {
        float a = vl[i] * inv;
        bf16 hv = __float2bfloat16_rn(a);
        ahr[tid + (i << 8)] = hv;
        alr[tid + (i << 8)] = __float2bfloat16_rn(a - __bfloat162float(hv));
    }
}

// ---------------- AV: ao = attn @ v ----------------
__global__ void __launch_bounds__(256, 2) mm_av(const bf16* ath, const bf16* atl,
                                                const bf16* vth, const bf16* vtl,
                                                bf16* aoh, bf16* aol) {
    int bh = blockIdx.z, b = bh >> 3, h = bh & 7;
    int m0 = blockIdx.y * 128;
    float acc[2][8][4];
    mm3_body(ath + (size_t)bh * T_ * T_, atl + (size_t)bh * T_ * T_, T_, m0, T_,
             vth + (size_t)bh * DK_ * T_, vtl + (size_t)bh * DK_ * T_, T_, 0, DK_,
             T_, acc);
    ACC_PAIRS(
        size_t idx = ((size_t)(b * T_ + m0 + rl)) * D_ + h * DK_ + cl;
        __nv_bfloat162 hh, ll;
        split2(v0, v1, hh, ll);
        *(__nv_bfloat162*)&aoh[idx] = hh;
        *(__nv_bfloat162*)&aol[idx] = ll;
    );
}

// ---------------- output projection ----------------
__global__ void __launch_bounds__(256, 2) mm_out(const bf16* aoh, const bf16* aol,
                                                 const bf16* woh, const bf16* wol,
                                                 float* __restrict__ out) {
    int m0 = blockIdx.y * 128, n0 = blockIdx.x * 128;
    float acc[2][8][4];
    mm3_body(aoh, aol, D_, m0, BT_, woh, wol, D_, n0, D_, D_, acc);
    ACC_PAIRS(
        *(float2*)&out[(size_t)(m0 + rl) * D_ + n0 + cl] = make_float2(v0, v1);
    );
}

// ---------------- launch ----------------
extern "C" void kernel_launch(void* const* d_in, const int* in_sizes, int n_in,
                              void* d_out, int out_size) {
    (void)in_sizes; (void)n_in; (void)out_size;
    const float* x  = (const float*)d_in[0];
    const float* pe = (const float*)d_in[1];
    const float* Wq = (const float*)d_in[2];
    const float* Wk = (const float*)d_in[3];
    const float* Wv = (const float*)d_in[4];
    const float* Wo = (const float*)d_in[5];
    const float* Wp = (const float*)d_in[6];
    const float* bu = (const float*)d_in[7];
    const float* bv = (const float*)d_in[8];

    bf16 *xh, *xl, *peh, *pel, *wqh, *wql, *wkh, *wkl, *wvh, *wvl, *woh, *wol, *wph, *wpl;
    bf16 *quh, *qul, *qvh, *qvl, *kh, *kl, *ph, *pl, *vth, *vtl, *ath, *atl, *aoh, *aol;
    float *v, *s;
    cudaGetSymbolAddress((void**)&xh,  g_xh);  cudaGetSymbolAddress((void**)&xl,  g_xl);
    cudaGetSymbolAddress((void**)&peh, g_peh); cudaGetSymbolAddress((void**)&pel, g_pel);
    cudaGetSymbolAddress((void**)&wqh, g_wqh); cudaGetSymbolAddress((void**)&wql, g_wql);
    cudaGetSymbolAddress((void**)&wkh, g_wkh); cudaGetSymbolAddress((void**)&wkl, g_wkl);
    cudaGetSymbolAddress((void**)&wvh, g_wvh); cudaGetSymbolAddress((void**)&wvl, g_wvl);
    cudaGetSymbolAddress((void**)&woh, g_woh); cudaGetSymbolAddress((void**)&wol, g_wol);
    cudaGetSymbolAddress((void**)&wph, g_wph); cudaGetSymbolAddress((void**)&wpl, g_wpl);
    cudaGetSymbolAddress((void**)&quh, g_quh); cudaGetSymbolAddress((void**)&qul, g_qul);
    cudaGetSymbolAddress((void**)&qvh, g_qvh); cudaGetSymbolAddress((void**)&qvl, g_qvl);
    cudaGetSymbolAddress((void**)&kh,  g_kh);  cudaGetSymbolAddress((void**)&kl,  g_kl);
    cudaGetSymbolAddress((void**)&ph,  g_ph);  cudaGetSymbolAddress((void**)&pl,  g_pl);
    cudaGetSymbolAddress((void**)&vth, g_vth); cudaGetSymbolAddress((void**)&vtl, g_vtl);
    cudaGetSymbolAddress((void**)&ath, g_ath); cudaGetSymbolAddress((void**)&atl, g_atl);
    cudaGetSymbolAddress((void**)&aoh, g_aoh); cudaGetSymbolAddress((void**)&aol, g_aol);
    cudaGetSymbolAddress((void**)&v,   g_v);
    cudaGetSymbolAddress((void**)&s,   g_s);

    cudaFuncSetAttribute(mm_proj,   cudaFuncAttributeMaxDynamicSharedMemorySize, SMEMSZ);
    cudaFuncSetAttribute(scores_ac, cudaFuncAttributeMaxDynamicSharedMemorySize, SMEMSZ);
    cudaFuncSetAttribute(scores_bd, cudaFuncAttributeMaxDynamicSharedMemorySize, SMEMSZ);
    cudaFuncSetAttribute(mm_av,     cudaFuncAttributeMaxDynamicSharedMemorySize, SMEMSZ);
    cudaFuncSetAttribute(mm_out,    cudaFuncAttributeMaxDynamicSharedMemorySize, SMEMSZ);

    // pre-split inputs to bf16 hi/lo
    splitk<<<(BT_ * D_ / 4 + 255) / 256, 256>>>(x,  xh,  xl,  BT_ * D_);
    splitk<<<(P_ * D_ / 4 + 255) / 256, 256>>>(pe, peh, pel, P_ * D_);
    splitk<<<(D_ * D_ / 4 + 255) / 256, 256>>>(Wq, wqh, wql, D_ * D_);
    splitk<<<(D_ * D_ / 4 + 255) / 256, 256>>>(Wk, wkh, wkl, D_ * D_);
    splitk<<<(D_ * D_ / 4 + 255) / 256, 256>>>(Wv, wvh, wvl, D_ * D_);
    splitk<<<(D_ * D_ / 4 + 255) / 256, 256>>>(Wo, woh, wol, D_ * D_);
    splitk<<<(D_ * D_ / 4 + 255) / 256, 256>>>(Wp, wph, wpl, D_ * D_);

    // projections (fused bias add + split in epilogue)
    mm_proj<<<dim3(D_ / 128, BT_ / 128, 4), 256, SMEMSZ>>>(
        xh, xl, peh, pel, wqh, wql, wkh, wkl, wvh, wvl, wph, wpl,
        bu, bv, quh, qul, qvh, qvl, kh, kl, v, ph, pl);

    // v transpose + split
    vtrans<<<dim3(T_ / 32, DK_ / 32, B_ * H_), 256>>>(v, vth, vtl);

    // scores: AC GEMM then banded BD GEMM in diagonal coordinates
    scores_ac<<<dim3(T_ / 128, T_ / 128, B_ * H_), 256, SMEMSZ>>>(quh, qul, kh, kl, s);
    scores_bd<<<dim3(17, T_ / 128, B_ * H_), 256, SMEMSZ>>>(qvh, qvl, ph, pl, s);

    // softmax -> bf16 hi/lo attn
    softmax_kernel<<<B_ * H_ * T_, 256>>>(s, ath, atl);

    // attn @ v
    mm_av<<<dim3(1, T_ / 128, B_ * H_), 256, SMEMSZ>>>(ath, atl, vth, vtl, aoh, aol);

    // output projection
    mm_out<<<dim3(D_ / 128, BT_ / 128, 1), 256, SMEMSZ>>>(aoh, aol, woh, wol, (float*)d_out);
}

// round 10
// speedup vs baseline: 2.2684x; 1.1974x over previous
#include <cuda_runtime.h>
#include <cuda_bf16.h>
#include <stdint.h>
#include <math.h>

#define B_  4
#define T_  2048
#define D_  1024
#define H_  8
#define DK_ 128
#define P_  (2*T_-1)
#define BT_ (B_*T_)

typedef __nv_bfloat16 bf16;

// ---------------- scratch (device globals: allocation-free) ----------------
static __device__ __align__(16) bf16 g_xh [(size_t)BT_ * D_];
static __device__ __align__(16) bf16 g_xl [(size_t)BT_ * D_];
static __device__ __align__(16) bf16 g_peh[(size_t)P_ * D_];
static __device__ __align__(16) bf16 g_pel[(size_t)P_ * D_];
static __device__ __align__(16) bf16 g_wqh[(size_t)D_ * D_], g_wql[(size_t)D_ * D_];
static __device__ __align__(16) bf16 g_wkh[(size_t)D_ * D_], g_wkl[(size_t)D_ * D_];
static __device__ __align__(16) bf16 g_wvh[(size_t)D_ * D_], g_wvl[(size_t)D_ * D_];
static __device__ __align__(16) bf16 g_woh[(size_t)D_ * D_], g_wol[(size_t)D_ * D_];
static __device__ __align__(16) bf16 g_wph[(size_t)D_ * D_], g_wpl[(size_t)D_ * D_];
static __device__ __align__(16) bf16 g_quh[(size_t)BT_ * D_], g_qul[(size_t)BT_ * D_];
static __device__ __align__(16) bf16 g_qvh[(size_t)BT_ * D_], g_qvl[(size_t)BT_ * D_];
static __device__ __align__(16) bf16 g_kh [(size_t)BT_ * D_], g_kl [(size_t)BT_ * D_];
static __device__ __align__(16) bf16 g_ph [(size_t)P_ * D_],  g_pl [(size_t)P_ * D_];
static __device__ __align__(16) float g_v [(size_t)BT_ * D_];
static __device__ __align__(16) bf16 g_vth[(size_t)B_ * H_ * DK_ * T_];
static __device__ __align__(16) bf16 g_vtl[(size_t)B_ * H_ * DK_ * T_];
static __device__ __align__(16) float g_s [(size_t)B_ * H_ * T_ * T_];
static __device__ __align__(16) bf16 g_ath[(size_t)B_ * H_ * T_ * T_];
static __device__ __align__(16) bf16 g_atl[(size_t)B_ * H_ * T_ * T_];
static __device__ __align__(16) bf16 g_aoh[(size_t)BT_ * D_], g_aol[(size_t)BT_ * D_];

// ============================ helpers ============================
__device__ __forceinline__ uint32_t smem_u32(const void* p) {
    uint32_t a;
    asm("{ .reg .u64 t; cvta.to.shared.u64 t, %1; cvt.u32.u64 %0, t; }" : "=r"(a) : "l"(p));
    return a;
}

__device__ __forceinline__ void split2(float a, float b, __nv_bfloat162& h, __nv_bfloat162& l) {
    bf16 ha = __float2bfloat16_rn(a), hb = __float2bfloat16_rn(b);
    h = __halves2bfloat162(ha, hb);
    l = __halves2bfloat162(__float2bfloat16_rn(a - __bfloat162float(ha)),
                           __float2bfloat16_rn(b - __bfloat162float(hb)));
}

#define LDSM4(r0, r1, r2, r3, addr) \
    asm volatile("ldmatrix.sync.aligned.m8n8.x4.shared.b16 {%0,%1,%2,%3}, [%4];" \
        : "=r"(r0), "=r"(r1), "=r"(r2), "=r"(r3) : "r"(addr))

#define MMA16816(c, a, b0, b1) \
    asm volatile("mma.sync.aligned.m16n8k16.row.col.f32.bf16.bf16.f32 " \
        "{%0,%1,%2,%3}, {%4,%5,%6,%7}, {%8,%9}, {%0,%1,%2,%3};" \
        : "+f"((c)[0]), "+f"((c)[1]), "+f"((c)[2]), "+f"((c)[3]) \
        : "r"((a)[0]), "r"((a)[1]), "r"((a)[2]), "r"((a)[3]), "r"(b0), "r"(b1))

#define CP16(dst, src, sz) \
    asm volatile("cp.async.cg.shared.global [%0], [%1], 16, %2;" \
        :: "r"(dst), "l"(src), "r"(sz))
#define CP_COMMIT() asm volatile("cp.async.commit_group;")
#define CP_WAIT(n)  asm volatile("cp.async.wait_group %0;" :: "n"(n))

// ---------------- split fp32 -> bf16 hi/lo ----------------
__global__ void __launch_bounds__(256) splitk(const float* __restrict__ s,
                                              bf16* __restrict__ h, bf16* __restrict__ l,
                                              int n) {
    int i = (blockIdx.x * 256 + threadIdx.x) * 4;
    if (i >= n) return;
    float4 v = *(const float4*)&s[i];
    __nv_bfloat162 h0, l0, h1, l1;
    split2(v.x, v.y, h0, l0);
    split2(v.z, v.w, h1, l1);
    *(__nv_bfloat162*)&h[i]     = h0;
    *(__nv_bfloat162*)&h[i + 2] = h1;
    *(__nv_bfloat162*)&l[i]     = l0;
    *(__nv_bfloat162*)&l[i + 2] = l1;
}

// ======== warp-MMA NT GEMM: 128x128 tile, cp.async double-buffered, K chunk 32 ========
// 256 threads, 8 warps 4(m)x2(n), warp tile 32x64. 3-combo hi/lo from resident frags.
#define KC    32
#define LDST  40                         // uint16 per smem row (80B, conflict-free ldmatrix)
#define ARRB  (128 * LDST * 2)           // bytes per array (10240)
#define SS    (4 * ARRB)                 // stage size 40960
#define SMEMSZ (2 * SS)                  // 81920
#define OFF_AH 0
#define OFF_AL ARRB
#define OFF_BH (2 * ARRB)
#define OFF_BL (3 * ARRB)

__device__ __forceinline__ void mm3_body(
        const bf16* __restrict__ Ah, const bf16* __restrict__ Al, int lda, int m0, int Mrows,
        const bf16* __restrict__ Bh, const bf16* __restrict__ Bl, int ldb, int n0, int Nrows,
        int K, float acc[2][8][4]) {
    extern __shared__ char dsm[];
    uint32_t sb = smem_u32(dsm);
    int tid = threadIdx.x, lane = tid & 31, wid = tid >> 5;
    int wm = (wid & 3) * 32, wn = (wid >> 2) * 64;
    int lr = lane & 15, lc8 = (lane >> 4) << 3;

    #pragma unroll
    for (int mt = 0; mt < 2; mt++)
        #pragma unroll
        for (int nt = 0; nt < 8; nt++)
            #pragma unroll
            for (int e = 0; e < 4; e++) acc[mt][nt][e] = 0.f;

    auto stage_fill = [&](int st, int kc) {
        uint32_t base = sb + st * SS;
        #pragma unroll
        for (int i = 0; i < 2; i++) {
            int sidx = tid + (i << 8);          // 0..511
            int row = sidx >> 2, seg = sidx & 3;
            int ar = m0 + row, br = n0 + row;
            int asz = (ar < Mrows) ? 16 : 0;
            int bsz = (br < Nrows) ? 16 : 0;
            uint32_t doff = row * (LDST * 2) + seg * 16;
            const char* pah = (const char*)(Ah + (size_t)ar * lda + kc) + seg * 16;
            const char* pal = (const char*)(Al + (size_t)ar * lda + kc) + seg * 16;
            const char* pbh = (const char*)(Bh + (size_t)br * ldb + kc) + seg * 16;
            const char* pbl = (const char*)(Bl + (size_t)br * ldb + kc) + seg * 16;
            CP16(base + OFF_AH + doff, pah, asz);
            CP16(base + OFF_AL + doff, pal, asz);
            CP16(base + OFF_BH + doff, pbh, bsz);
            CP16(base + OFF_BL + doff, pbl, bsz);
        }
    };

    const int NC = K / KC;
    stage_fill(0, 0);
    CP_COMMIT();

    for (int c = 0; c < NC; c++) {
        int st = c & 1;
        if (c + 1 < NC) {
            stage_fill(st ^ 1, (c + 1) * KC);
            CP_COMMIT();
            CP_WAIT(1);
        } else {
            CP_WAIT(0);
        }
        __syncthreads();

        uint32_t abase = sb + st * SS;
        #pragma unroll
        for (int kk = 0; kk < KC; kk += 16) {
            uint32_t ah[2][4], al[2][4];
            #pragma unroll
            for (int mt = 0; mt < 2; mt++) {
                uint32_t r = abase + OFF_AH + (wm + mt * 16 + lr) * (LDST * 2) + (kk + lc8) * 2;
                LDSM4(ah[mt][0], ah[mt][1], ah[mt][2], ah[mt][3], r);
                r = abase + OFF_AL + (wm + mt * 16 + lr) * (LDST * 2) + (kk + lc8) * 2;
                LDSM4(al[mt][0], al[mt][1], al[mt][2], al[mt][3], r);
            }
            #pragma unroll
            for (int g = 0; g < 4; g++) {
                uint32_t bh0, bh1, bh2, bh3, bl0, bl1, bl2, bl3;
                uint32_t r = abase + OFF_BH + (wn + g * 16 + lr) * (LDST * 2) + (kk + lc8) * 2;
                LDSM4(bh0, bh1, bh2, bh3, r);
                r = abase + OFF_BL + (wn + g * 16 + lr) * (LDST * 2) + (kk + lc8) * 2;
                LDSM4(bl0, bl1, bl2, bl3, r);
                #pragma unroll
                for (int mt = 0; mt < 2; mt++) {
                    MMA16816(acc[mt][2 * g],     ah[mt], bh0, bh2);
                    MMA16816(acc[mt][2 * g + 1], ah[mt], bh1, bh3);
                    MMA16816(acc[mt][2 * g],     ah[mt], bl0, bl2);
                    MMA16816(acc[mt][2 * g + 1], ah[mt], bl1, bl3);
                    MMA16816(acc[mt][2 * g],     al[mt], bh0, bh2);
                    MMA16816(acc[mt][2 * g + 1], al[mt], bh1, bh3);
                }
            }
        }
        __syncthreads();
    }
}

// iterate accumulator as float2 pairs: rl/cl local row/col, v0/v1 values
#define ACC_PAIRS(...) do {                                                   \
    int lane = threadIdx.x & 31, wid = threadIdx.x >> 5;                      \
    int wm = (wid & 3) * 32, wn = (wid >> 2) * 64;                            \
    int g = lane >> 2, tg = lane & 3;                                         \
    _Pragma("unroll") for (int mt = 0; mt < 2; mt++)                          \
    _Pragma("unroll") for (int hf = 0; hf < 2; hf++) {                        \
        int rl = wm + mt * 16 + g + hf * 8;                                   \
        _Pragma("unroll") for (int nt = 0; nt < 8; nt++) {                    \
            int cl = wn + nt * 8 + tg * 2;                                    \
            float v0 = acc[mt][nt][hf * 2], v1 = acc[mt][nt][hf * 2 + 1];     \
            { __VA_ARGS__ }                                                   \
        }                                                                     \
    }                                                                         \
} while (0)

// ---------------- projections: z=0 q(+biases), 1 k, 2 v, 3 p ----------------
__global__ void __launch_bounds__(256, 2) mm_proj(
        const bf16* xh, const bf16* xl, const bf16* peh, const bf16* pel,
        const bf16* wqh, const bf16* wql, const bf16* wkh, const bf16* wkl,
        const bf16* wvh, const bf16* wvl, const bf16* wph, const bf16* wpl,
        const float* bu, const float* bv,
        bf16* quh, bf16* qul, bf16* qvh, bf16* qvl,
        bf16* kh, bf16* kl, float* v, bf16* ph, bf16* pl) {
    int z = blockIdx.z;
    const bf16* Ah = (z == 3) ? peh : xh;
    const bf16* Al = (z == 3) ? pel : xl;
    const bf16* Bh = (z == 0) ? wqh : (z == 1) ? wkh : (z == 2) ? wvh : wph;
    const bf16* Bl = (z == 0) ? wql : (z == 1) ? wkl : (z == 2) ? wvl : wpl;
    int M = (z == 3) ? P_ : BT_;
    int m0 = blockIdx.y * 128;
    if (m0 >= M) return;
    int n0 = blockIdx.x * 128;
    float acc[2][8][4];
    mm3_body(Ah, Al, D_, m0, M, Bh, Bl, D_, n0, D_, D_, acc);

    if (z == 0) {
        ACC_PAIRS(
            int r = m0 + rl, c = n0 + cl;
            size_t idx = (size_t)r * D_ + c;
            __nv_bfloat162 h, l;
            split2(v0 + __ldg(&bu[c]), v1 + __ldg(&bu[c + 1]), h, l);
            *(__nv_bfloat162*)&quh[idx] = h; *(__nv_bfloat162*)&qul[idx] = l;
            split2(v0 + __ldg(&bv[c]), v1 + __ldg(&bv[c + 1]), h, l);
            *(__nv_bfloat162*)&qvh[idx] = h; *(__nv_bfloat162*)&qvl[idx] = l;
        );
    } else if (z == 1) {
        ACC_PAIRS(
            size_t idx = (size_t)(m0 + rl) * D_ + n0 + cl;
            __nv_bfloat162 h, l;
            split2(v0, v1, h, l);
            *(__nv_bfloat162*)&kh[idx] = h; *(__nv_bfloat162*)&kl[idx] = l;
        );
    } else if (z == 2) {
        ACC_PAIRS(
            *(float2*)&v[(size_t)(m0 + rl) * D_ + n0 + cl] = make_float2(v0, v1);
        );
    } else {
        ACC_PAIRS(
            int r = m0 + rl;
            if (r < P_) {
                size_t idx = (size_t)r * D_ + n0 + cl;
                __nv_bfloat162 h, l;
                split2(v0, v1, h, l);
                *(__nv_bfloat162*)&ph[idx] = h; *(__nv_bfloat162*)&pl[idx] = l;
            }
        );
    }
}

// ---------------- scores AC: S = (q+u)·k^T * scale ----------------
__global__ void __launch_bounds__(256, 2) scores_ac(const bf16* quh, const bf16* qul,
                                                    const bf16* kh, const bf16* kl,
                                                    float* __restrict__ s) {
    int bh = blockIdx.z, b = bh >> 3, h = bh & 7;
    size_t base = (size_t)b * T_ * D_ + h * DK_;
    int m0 = blockIdx.y * 128, n0 = blockIdx.x * 128;
    float acc[2][8][4];
    mm3_body(quh + base, qul + base, D_, m0, T_, kh + base, kl + base, D_, n0, T_, DK_, acc);
    const float scale = 0.08838834764831845f;
    float* sout = s + (size_t)bh * T_ * T_;
    ACC_PAIRS(
        *(float2*)&sout[(size_t)(m0 + rl) * T_ + n0 + cl] =
            make_float2(v0 * scale, v1 * scale);
    );
}

// ---------------- scores BD (diagonal GEMM): S[q][j+q-(T-1)] += (q+v)·p[j] * scale
__global__ void __launch_bounds__(256, 2) scores_bd(const bf16* qvh, const bf16* qvl,
                                                    const bf16* ph, const bf16* pl,
                                                    float* __restrict__ s) {
    int bh = blockIdx.z, b = bh >> 3, h = bh & 7;
    int qi = blockIdx.y;
    int j0 = (15 - qi + (int)blockIdx.x) * 128;
    size_t abase = (size_t)b * T_ * D_ + h * DK_;
    int m0 = qi * 128;
    float acc[2][8][4];
    mm3_body(qvh + abase, qvl + abase, D_, m0, T_,
             ph + h * DK_, pl + h * DK_, D_, j0, P_, DK_, acc);
    const float scale = 0.08838834764831845f;
    float* sout = s + (size_t)bh * T_ * T_;
    ACC_PAIRS(
        int q = m0 + rl;
        int k = j0 + cl + q - (T_ - 1);
        float* row = &sout[(size_t)q * T_];
        if ((unsigned)k < (unsigned)T_)       row[k]     += v0 * scale;
        if ((unsigned)(k + 1) < (unsigned)T_) row[k + 1] += v1 * scale;
    );
}

// ---------------- v transpose + split: vt[bh][dk][t] ----------------
__global__ void __launch_bounds__(256) vtrans(const float* __restrict__ v,
                                              bf16* __restrict__ vth,
                                              bf16* __restrict__ vtl) {
    __shared__ float tile[32][33];
    int bh = blockIdx.z, b = bh >> 3, h = bh & 7;
    int t0 = blockIdx.x * 32, d0 = blockIdx.y * 32;
    int tx = threadIdx.x & 31, ty = threadIdx.x >> 5;
    #pragma unroll
    for (int i = 0; i < 4; ++i) {
        int t = t0 + ty + i * 8;
        tile[ty + i * 8][tx] = v[(size_t)(b * T_ + t) * D_ + h * DK_ + d0 + tx];
    }
    __syncthreads();
    #pragma unroll
    for (int i = 0; i < 4; ++i) {
        int dk = d0 + ty + i * 8;
        float val = tile[tx][ty + i * 8];
        bf16 hv = __float2bfloat16_rn(val);
        size_t idx = ((size_t)bh * DK_ + dk) * T_ + t0 + tx;
        vth[idx] = hv;
        vtl[idx] = __float2bfloat16_rn(val - __bfloat162float(hv));
    }
}

// ---------------- softmax: fp32 scores -> bf16 hi/lo attn ----------------
__global__ void __launch_bounds__(256) softmax_kernel(const float* __restrict__ s,
                                                      bf16* __restrict__ ah,
                                                      bf16* __restrict__ al) {
    const float* sr = s + (size_t)blockIdx.x * T_;
    bf16* ahr = ah + (size_t)blockIdx.x * T_;
    bf16* alr = al + (size_t)blockIdx.x * T_;
    int tid = threadIdx.x;
    float vl[8];
    float m = -1e30f;
    #pragma unroll
    for (int i = 0; i < 8; i++) { vl[i] = sr[tid + (i << 8)]; m = fmaxf(m, vl[i]); }
    #pragma unroll
    for (int o = 16; o; o >>= 1) m = fmaxf(m, __shfl_xor_sync(0xffffffffu, m, o));
    __shared__ float rmax[8], rsum[8];
    if ((tid & 31) == 0) rmax[tid >> 5] = m;
    __syncthreads();
    if (tid == 0) {
        float mm = rmax[0];
        for (int i = 1; i < 8; i++) mm = fmaxf(mm, rmax[i]);
        rmax[0] = mm;
    }
    __syncthreads();
    m = rmax[0];
    float sum = 0.f;
    #pragma unroll
    for (int i = 0; i < 8; i++) { vl[i] = __expf(vl[i] - m); sum += vl[i]; }
    #pragma unroll
    for (int o = 16; o; o >>= 1) sum += __shfl_xor_sync(0xffffffffu, sum, o);
    if ((tid & 31) == 0) rsum[tid >> 5] = sum;
    __syncthreads();
    if (tid == 0) {
        float ss = rsum[0];
        for (int i = 1; i < 8; i++) ss += rsum[i];
        rsum[0] = ss;
    }
    __syncthreads();
    float inv = 1.0f / rsum[0];
    #pragma unroll
    for (int i = 0; i < 8; i++) {
        float a = vl[i] * inv;
        bf16 hv = __float2bfloat16_rn(a);
        ahr[tid + (i << 8)] = hv;
        alr[tid + (i << 8)] = __float2bfloat16_rn(a - __bfloat162float(hv));
    }
}

// ---------------- AV: ao = attn @ v ----------------
__global__ void __launch_bounds__(256, 2) mm_av(const bf16* ath, const bf16* atl,
                                                const bf16* vth, const bf16* vtl,
                                                bf16* aoh, bf16* aol) {
    int bh = blockIdx.z, b = bh >> 3, h = bh & 7;
    int m0 = blockIdx.y * 128;
    float acc[2][8][4];
    mm3_body(ath + (size_t)bh * T_ * T_, atl + (size_t)bh * T_ * T_, T_, m0, T_,
             vth + (size_t)bh * DK_ * T_, vtl + (size_t)bh * DK_ * T_, T_, 0, DK_,
             T_, acc);
    ACC_PAIRS(
        size_t idx = ((size_t)(b * T_ + m0 + rl)) * D_ + h * DK_ + cl;
        __nv_bfloat162 hh, ll;
        split2(v0, v1, hh, ll);
        *(__nv_bfloat162*)&aoh[idx] = hh;
        *(__nv_bfloat162*)&aol[idx] = ll;
    );
}

// ---------------- output projection ----------------
__global__ void __launch_bounds__(256, 2) mm_out(const bf16* aoh, const bf16* aol,
                                                 const bf16* woh, const bf16* wol,
                                                 float* __restrict__ out) {
    int m0 = blockIdx.y * 128, n0 = blockIdx.x * 128;
    float acc[2][8][4];
    mm3_body(aoh, aol, D_, m0, BT_, woh, wol, D_, n0, D_, D_, acc);
    ACC_PAIRS(
        *(float2*)&out[(size_t)(m0 + rl) * D_ + n0 + cl] = make_float2(v0, v1);
    );
}

// ---------------- launch ----------------
extern "C" void kernel_launch(void* const* d_in, const int* in_sizes, int n_in,
                              void* d_out, int out_size) {
    (void)in_sizes; (void)n_in; (void)out_size;
    const float* x  = (const float*)d_in[0];
    const float* pe = (const float*)d_in[1];
    const float* Wq = (const float*)d_in[2];
    const float* Wk = (const float*)d_in[3];
    const float* Wv = (const float*)d_in[4];
    const float* Wo = (const float*)d_in[5];
    const float* Wp = (const float*)d_in[6];
    const float* bu = (const float*)d_in[7];
    const float* bv = (const float*)d_in[8];

    bf16 *xh, *xl, *peh, *pel, *wqh, *wql, *wkh, *wkl, *wvh, *wvl, *woh, *wol, *wph, *wpl;
    bf16 *quh, *qul, *qvh, *qvl, *kh, *kl, *ph, *pl, *vth, *vtl, *ath, *atl, *aoh, *aol;
    float *v, *s;
    cudaGetSymbolAddress((void**)&xh,  g_xh);  cudaGetSymbolAddress((void**)&xl,  g_xl);
    cudaGetSymbolAddress((void**)&peh, g_peh); cudaGetSymbolAddress((void**)&pel, g_pel);
    cudaGetSymbolAddress((void**)&wqh, g_wqh); cudaGetSymbolAddress((void**)&wql, g_wql);
    cudaGetSymbolAddress((void**)&wkh, g_wkh); cudaGetSymbolAddress((void**)&wkl, g_wkl);
    cudaGetSymbolAddress((void**)&wvh, g_wvh); cudaGetSymbolAddress((void**)&wvl, g_wvl);
    cudaGetSymbolAddress((void**)&woh, g_woh); cudaGetSymbolAddress((void**)&wol, g_wol);
    cudaGetSymbolAddress((void**)&wph, g_wph); cudaGetSymbolAddress((void**)&wpl, g_wpl);
    cudaGetSymbolAddress((void**)&quh, g_quh); cudaGetSymbolAddress((void**)&qul, g_qul);
    cudaGetSymbolAddress((void**)&qvh, g_qvh); cudaGetSymbolAddress((void**)&qvl, g_qvl);
    cudaGetSymbolAddress((void**)&kh,  g_kh);  cudaGetSymbolAddress((void**)&kl,  g_kl);
    cudaGetSymbolAddress((void**)&ph,  g_ph);  cudaGetSymbolAddress((void**)&pl,  g_pl);
    cudaGetSymbolAddress((void**)&vth, g_vth); cudaGetSymbolAddress((void**)&vtl, g_vtl);
    cudaGetSymbolAddress((void**)&ath, g_ath); cudaGetSymbolAddress((void**)&atl, g_atl);
    cudaGetSymbolAddress((void**)&aoh, g_aoh); cudaGetSymbolAddress((void**)&aol, g_aol);
    cudaGetSymbolAddress((void**)&v,   g_v);
    cudaGetSymbolAddress((void**)&s,   g_s);

    cudaFuncSetAttribute(mm_proj,   cudaFuncAttributeMaxDynamicSharedMemorySize, SMEMSZ);
    cudaFuncSetAttribute(scores_ac, cudaFuncAttributeMaxDynamicSharedMemorySize, SMEMSZ);
    cudaFuncSetAttribute(scores_bd, cudaFuncAttributeMaxDynamicSharedMemorySize, SMEMSZ);
    cudaFuncSetAttribute(mm_av,     cudaFuncAttributeMaxDynamicSharedMemorySize, SMEMSZ);
    cudaFuncSetAttribute(mm_out,    cudaFuncAttributeMaxDynamicSharedMemorySize, SMEMSZ);

    // pre-split inputs to bf16 hi/lo
    splitk<<<(BT_ * D_ / 4 + 255) / 256, 256>>>(x,  xh,  xl,  BT_ * D_);
    splitk<<<(P_ * D_ / 4 + 255) / 256, 256>>>(pe, peh, pel, P_ * D_);
    splitk<<<(D_ * D_ / 4 + 255) / 256, 256>>>(Wq, wqh, wql, D_ * D_);
    splitk<<<(D_ * D_ / 4 + 255) / 256, 256>>>(Wk, wkh, wkl, D_ * D_);
    splitk<<<(D_ * D_ / 4 + 255) / 256, 256>>>(Wv, wvh, wvl, D_ * D_);
    splitk<<<(D_ * D_ / 4 + 255) / 256, 256>>>(Wo, woh, wol, D_ * D_);
    splitk<<<(D_ * D_ / 4 + 255) / 256, 256>>>(Wp, wph, wpl, D_ * D_);

    // projections (fused bias add + split in epilogue)
    mm_proj<<<dim3(D_ / 128, BT_ / 128, 4), 256, SMEMSZ>>>(
        xh, xl, peh, pel, wqh, wql, wkh, wkl, wvh, wvl, wph, wpl,
        bu, bv, quh, qul, qvh, qvl, kh, kl, v, ph, pl);

    // v transpose + split
    vtrans<<<dim3(T_ / 32, DK_ / 32, B_ * H_), 256>>>(v, vth, vtl);

    // scores: AC GEMM then banded BD GEMM in diagonal coordinates
    scores_ac<<<dim3(T_ / 128, T_ / 128, B_ * H_), 256, SMEMSZ>>>(quh, qul, kh, kl, s);
    scores_bd<<<dim3(17, T_ / 128, B_ * H_), 256, SMEMSZ>>>(qvh, qvl, ph, pl, s);

    // softmax -> bf16 hi/lo attn
    softmax_kernel<<<B_ * H_ * T_, 256>>>(s, ath, atl);

    // attn @ v
    mm_av<<<dim3(1, T_ / 128, B_ * H_), 256, SMEMSZ>>>(ath, atl, vth, vtl, aoh, aol);

    // output projection
    mm_out<<<dim3(D_ / 128, BT_ / 128, 1), 256, SMEMSZ>>>(aoh, aol, woh, wol, (float*)d_out);
}

// round 11
// speedup vs baseline: 2.8641x; 1.2626x over previous
#include <cuda_runtime.h>
#include <cuda_fp16.h>
#include <stdint.h>
#include <math.h>

#define B_  4
#define T_  2048
#define D_  1024
#define H_  8
#define DK_ 128
#define P_  (2*T_-1)
#define BT_ (B_*T_)

typedef __half f16;

// ---------------- scratch (device globals: allocation-free) ----------------
static __device__ __align__(16) f16 g_xh [(size_t)BT_ * D_];
static __device__ __align__(16) f16 g_peh[(size_t)P_ * D_];
static __device__ __align__(16) f16 g_wqh[(size_t)D_ * D_], g_wql[(size_t)D_ * D_];
static __device__ __align__(16) f16 g_wkh[(size_t)D_ * D_], g_wkl[(size_t)D_ * D_];
static __device__ __align__(16) f16 g_wvh[(size_t)D_ * D_], g_wvl[(size_t)D_ * D_];
static __device__ __align__(16) f16 g_woh[(size_t)D_ * D_], g_wol[(size_t)D_ * D_];
static __device__ __align__(16) f16 g_wph[(size_t)D_ * D_], g_wpl[(size_t)D_ * D_];
static __device__ __align__(16) f16 g_quh[(size_t)BT_ * D_];
static __device__ __align__(16) f16 g_qvh[(size_t)BT_ * D_];
static __device__ __align__(16) f16 g_kh [(size_t)BT_ * D_], g_kl [(size_t)BT_ * D_];
static __device__ __align__(16) f16 g_ph [(size_t)P_ * D_],  g_pl [(size_t)P_ * D_];
static __device__ __align__(16) float g_v [(size_t)BT_ * D_];
static __device__ __align__(16) f16 g_vth[(size_t)B_ * H_ * DK_ * T_];
static __device__ __align__(16) f16 g_vtl[(size_t)B_ * H_ * DK_ * T_];
static __device__ __align__(16) float g_s [(size_t)B_ * H_ * T_ * T_];
static __device__ __align__(16) f16 g_ath[(size_t)B_ * H_ * T_ * T_];
static __device__ __align__(16) f16 g_aoh[(size_t)BT_ * D_];

// ============================ helpers ============================
__device__ __forceinline__ uint32_t smem_u32(const void* p) {
    uint32_t a;
    asm("{ .reg .u64 t; cvta.to.shared.u64 t, %1; cvt.u32.u64 %0, t; }" : "=r"(a) : "l"(p));
    return a;
}

__device__ __forceinline__ void split2h(float a, float b, __half2& h, __half2& l) {
    f16 ha = __float2half_rn(a), hb = __float2half_rn(b);
    h = __halves2half2(ha, hb);
    l = __halves2half2(__float2half_rn(a - __half2float(ha)),
                       __float2half_rn(b - __half2float(hb)));
}

#define LDSM4(r0, r1, r2, r3, addr) \
    asm volatile("ldmatrix.sync.aligned.m8n8.x4.shared.b16 {%0,%1,%2,%3}, [%4];" \
        : "=r"(r0), "=r"(r1), "=r"(r2), "=r"(r3) : "r"(addr))

#define MMA16816(c, a, b0, b1) \
    asm volatile("mma.sync.aligned.m16n8k16.row.col.f32.f16.f16.f32 " \
        "{%0,%1,%2,%3}, {%4,%5,%6,%7}, {%8,%9}, {%0,%1,%2,%3};" \
        : "+f"((c)[0]), "+f"((c)[1]), "+f"((c)[2]), "+f"((c)[3]) \
        : "r"((a)[0]), "r"((a)[1]), "r"((a)[2]), "r"((a)[3]), "r"(b0), "r"(b1))

#define CP16(dst, src, sz) \
    asm volatile("cp.async.cg.shared.global [%0], [%1], 16, %2;" \
        :: "r"(dst), "l"(src), "r"(sz))
#define CP_COMMIT() asm volatile("cp.async.commit_group;")
#define CP_WAIT(n)  asm volatile("cp.async.wait_group %0;" :: "n"(n))

// ---------------- convert fp32 -> fp16 ----------------
__global__ void __launch_bounds__(256) cvt_h(const float* __restrict__ s,
                                             f16* __restrict__ h, int n) {
    int i = (blockIdx.x * 256 + threadIdx.x) * 4;
    if (i >= n) return;
    float4 v = *(const float4*)&s[i];
    __half2 a = __halves2half2(__float2half_rn(v.x), __float2half_rn(v.y));
    __half2 b = __halves2half2(__float2half_rn(v.z), __float2half_rn(v.w));
    *(__half2*)&h[i]     = a;
    *(__half2*)&h[i + 2] = b;
}

// ---------------- split fp32 -> fp16 hi/lo ----------------
__global__ void __launch_bounds__(256) splitk(const float* __restrict__ s,
                                              f16* __restrict__ h, f16* __restrict__ l,
                                              int n) {
    int i = (blockIdx.x * 256 + threadIdx.x) * 4;
    if (i >= n) return;
    float4 v = *(const float4*)&s[i];
    __half2 h0, l0, h1, l1;
    split2h(v.x, v.y, h0, l0);
    split2h(v.z, v.w, h1, l1);
    *(__half2*)&h[i]     = h0;
    *(__half2*)&h[i + 2] = h1;
    *(__half2*)&l[i]     = l0;
    *(__half2*)&l[i + 2] = l1;
}

// ======== warp-MMA NT GEMM: 128x128 tile, A fp16, B fp16 hi/lo, 2 passes ========
// 256 threads, 8 warps 4(m)x2(n), warp tile 32x64, K chunk 32, 3-stage cp.async.
#define KC    32
#define LDST  40                          // uint16 per smem row (80B, conflict-free)
#define ARRB  (128 * LDST * 2)            // 10240 bytes per array
#define SS    (3 * ARRB)                  // stage = AH + BH + BL = 30720
#define NSTG  3
#define SMEMSZ (NSTG * SS)                // 92160
#define OFF_AH 0
#define OFF_BH ARRB
#define OFF_BL (2 * ARRB)

__device__ __forceinline__ void mm2_body(
        const f16* __restrict__ Ah, int lda, int m0, int Mrows,
        const f16* __restrict__ Bh, const f16* __restrict__ Bl, int ldb, int n0, int Nrows,
        int K, float acc[2][8][4]) {
    extern __shared__ char dsm[];
    uint32_t sb = smem_u32(dsm);
    int tid = threadIdx.x, lane = tid & 31, wid = tid >> 5;
    int wm = (wid & 3) * 32, wn = (wid >> 2) * 64;
    int lr = lane & 15, lc8 = (lane >> 4) << 3;

    #pragma unroll
    for (int mt = 0; mt < 2; mt++)
        #pragma unroll
        for (int nt = 0; nt < 8; nt++)
            #pragma unroll
            for (int e = 0; e < 4; e++) acc[mt][nt][e] = 0.f;

    auto stage_fill = [&](int st, int kc) {
        uint32_t base = sb + st * SS;
        #pragma unroll
        for (int i = 0; i < 6; i++) {
            int sidx = tid + (i << 8);          // 0..1535
            int arr = sidx >> 9;                // 0=AH,1=BH,2=BL
            int rem = sidx & 511;
            int row = rem >> 2, seg = rem & 3;
            uint32_t doff = arr * ARRB + row * (LDST * 2) + seg * 16;
            const char* src;
            int sz;
            if (arr == 0) {
                int r = m0 + row;
                src = (const char*)(Ah + (size_t)r * lda + kc) + seg * 16;
                sz = (r < Mrows) ? 16 : 0;
            } else if (arr == 1) {
                int r = n0 + row;
                src = (const char*)(Bh + (size_t)r * ldb + kc) + seg * 16;
                sz = (r < Nrows) ? 16 : 0;
            } else {
                int r = n0 + row;
                src = (const char*)(Bl + (size_t)r * ldb + kc) + seg * 16;
                sz = (r < Nrows) ? 16 : 0;
            }
            CP16(base + doff, src, sz);
        }
    };

    const int NC = K / KC;
    stage_fill(0, 0);
    CP_COMMIT();
    if (NC > 1) { stage_fill(1, KC); CP_COMMIT(); }

    for (int c = 0; c < NC; c++) {
        if (c < NC - 1) CP_WAIT(1); else CP_WAIT(0);
        __syncthreads();

        uint32_t abase = sb + (c % NSTG) * SS;
        #pragma unroll
        for (int kk = 0; kk < KC; kk += 16) {
            uint32_t ah[2][4];
            #pragma unroll
            for (int mt = 0; mt < 2; mt++) {
                uint32_t r = abase + OFF_AH + (wm + mt * 16 + lr) * (LDST * 2) + (kk + lc8) * 2;
                LDSM4(ah[mt][0], ah[mt][1], ah[mt][2], ah[mt][3], r);
            }
            #pragma unroll
            for (int g = 0; g < 4; g++) {
                uint32_t bh0, bh1, bh2, bh3, bl0, bl1, bl2, bl3;
                uint32_t r = abase + OFF_BH + (wn + g * 16 + lr) * (LDST * 2) + (kk + lc8) * 2;
                LDSM4(bh0, bh1, bh2, bh3, r);
                r = abase + OFF_BL + (wn + g * 16 + lr) * (LDST * 2) + (kk + lc8) * 2;
                LDSM4(bl0, bl1, bl2, bl3, r);
                #pragma unroll
                for (int mt = 0; mt < 2; mt++) {
                    MMA16816(acc[mt][2 * g],     ah[mt], bh0, bh2);
                    MMA16816(acc[mt][2 * g + 1], ah[mt], bh1, bh3);
                    MMA16816(acc[mt][2 * g],     ah[mt], bl0, bl2);
                    MMA16816(acc[mt][2 * g + 1], ah[mt], bl1, bl3);
                }
            }
        }
        if (c + 2 < NC) { stage_fill((c + 2) % NSTG, (c + 2) * KC); CP_COMMIT(); }
    }
}

// iterate accumulator as float2 pairs: rl/cl local row/col, v0/v1 values
#define ACC_PAIRS(...) do {                                                   \
    int lane = threadIdx.x & 31, wid = threadIdx.x >> 5;                      \
    int wm = (wid & 3) * 32, wn = (wid >> 2) * 64;                            \
    int g = lane >> 2, tg = lane & 3;                                         \
    _Pragma("unroll") for (int mt = 0; mt < 2; mt++)                          \
    _Pragma("unroll") for (int hf = 0; hf < 2; hf++) {                        \
        int rl = wm + mt * 16 + g + hf * 8;                                   \
        _Pragma("unroll") for (int nt = 0; nt < 8; nt++) {                    \
            int cl = wn + nt * 8 + tg * 2;                                    \
            float v0 = acc[mt][nt][hf * 2], v1 = acc[mt][nt][hf * 2 + 1];     \
            { __VA_ARGS__ }                                                   \
        }                                                                     \
    }                                                                         \
} while (0)

// ---------------- projections: z=0 q(+biases), 1 k, 2 v, 3 p ----------------
__global__ void __launch_bounds__(256, 2) mm_proj(
        const f16* xh, const f16* peh,
        const f16* wqh, const f16* wql, const f16* wkh, const f16* wkl,
        const f16* wvh, const f16* wvl, const f16* wph, const f16* wpl,
        const float* bu, const float* bv,
        f16* quh, f16* qvh, f16* kh, f16* kl, float* v, f16* ph, f16* pl) {
    int z = blockIdx.z;
    const f16* Ah = (z == 3) ? peh : xh;
    const f16* Bh = (z == 0) ? wqh : (z == 1) ? wkh : (z == 2) ? wvh : wph;
    const f16* Bl = (z == 0) ? wql : (z == 1) ? wkl : (z == 2) ? wvl : wpl;
    int M = (z == 3) ? P_ : BT_;
    int m0 = blockIdx.y * 128;
    if (m0 >= M) return;
    int n0 = blockIdx.x * 128;
    float acc[2][8][4];
    mm2_body(Ah, D_, m0, M, Bh, Bl, D_, n0, D_, D_, acc);

    if (z == 0) {
        ACC_PAIRS(
            int r = m0 + rl, c = n0 + cl;
            size_t idx = (size_t)r * D_ + c;
            *(__half2*)&quh[idx] = __halves2half2(
                __float2half_rn(v0 + __ldg(&bu[c])), __float2half_rn(v1 + __ldg(&bu[c + 1])));
            *(__half2*)&qvh[idx] = __halves2half2(
                __float2half_rn(v0 + __ldg(&bv[c])), __float2half_rn(v1 + __ldg(&bv[c + 1])));
        );
    } else if (z == 1) {
        ACC_PAIRS(
            size_t idx = (size_t)(m0 + rl) * D_ + n0 + cl;
            __half2 h, l;
            split2h(v0, v1, h, l);
            *(__half2*)&kh[idx] = h; *(__half2*)&kl[idx] = l;
        );
    } else if (z == 2) {
        ACC_PAIRS(
            *(float2*)&v[(size_t)(m0 + rl) * D_ + n0 + cl] = make_float2(v0, v1);
        );
    } else {
        ACC_PAIRS(
            int r = m0 + rl;
            if (r < P_) {
                size_t idx = (size_t)r * D_ + n0 + cl;
                __half2 h, l;
                split2h(v0, v1, h, l);
                *(__half2*)&ph[idx] = h; *(__half2*)&pl[idx] = l;
            }
        );
    }
}

// ---------------- scores AC: S = (q+u)·k^T * scale ----------------
__global__ void __launch_bounds__(256, 2) scores_ac(const f16* quh,
                                                    const f16* kh, const f16* kl,
                                                    float* __restrict__ s) {
    int bh = blockIdx.z, b = bh >> 3, h = bh & 7;
    size_t base = (size_t)b * T_ * D_ + h * DK_;
    int m0 = blockIdx.y * 128, n0 = blockIdx.x * 128;
    float acc[2][8][4];
    mm2_body(quh + base, D_, m0, T_, kh + base, kl + base, D_, n0, T_, DK_, acc);
    const float scale = 0.08838834764831845f;
    float* sout = s + (size_t)bh * T_ * T_;
    ACC_PAIRS(
        *(float2*)&sout[(size_t)(m0 + rl) * T_ + n0 + cl] =
            make_float2(v0 * scale, v1 * scale);
    );
}

// ---------------- scores BD (diagonal GEMM): S[q][j+q-(T-1)] += (q+v)·p[j] * scale
__global__ void __launch_bounds__(256, 2) scores_bd(const f16* qvh,
                                                    const f16* ph, const f16* pl,
                                                    float* __restrict__ s) {
    int bh = blockIdx.z, b = bh >> 3, h = bh & 7;
    int qi = blockIdx.y;
    int j0 = (15 - qi + (int)blockIdx.x) * 128;
    size_t abase = (size_t)b * T_ * D_ + h * DK_;
    int m0 = qi * 128;
    float acc[2][8][4];
    mm2_body(qvh + abase, D_, m0, T_, ph + h * DK_, pl + h * DK_, D_, j0, P_, DK_, acc);
    const float scale = 0.08838834764831845f;
    float* sout = s + (size_t)bh * T_ * T_;
    ACC_PAIRS(
        int q = m0 + rl;
        int k = j0 + cl + q - (T_ - 1);
        float* row = &sout[(size_t)q * T_];
        if ((unsigned)k < (unsigned)T_)       row[k]     += v0 * scale;
        if ((unsigned)(k + 1) < (unsigned)T_) row[k + 1] += v1 * scale;
    );
}

// ---------------- v transpose + split: vt[bh][dk][t] ----------------
__global__ void __launch_bounds__(256) vtrans(const float* __restrict__ v,
                                              f16* __restrict__ vth,
                                              f16* __restrict__ vtl) {
    __shared__ float tile[32][33];
    int bh = blockIdx.z, b = bh >> 3, h = bh & 7;
    int t0 = blockIdx.x * 32, d0 = blockIdx.y * 32;
    int tx = threadIdx.x & 31, ty = threadIdx.x >> 5;
    #pragma unroll
    for (int i = 0; i < 4; ++i) {
        int t = t0 + ty + i * 8;
        tile[ty + i * 8][tx] = v[(size_t)(b * T_ + t) * D_ + h * DK_ + d0 + tx];
    }
    __syncthreads();
    #pragma unroll
    for (int i = 0; i < 4; ++i) {
        int dk = d0 + ty + i * 8;
        float val = tile[tx][ty + i * 8];
        f16 hv = __float2half_rn(val);
        size_t idx = ((size_t)bh * DK_ + dk) * T_ + t0 + tx;
        vth[idx] = hv;
        vtl[idx] = __float2half_rn(val - __half2float(hv));
    }
}

// ---------------- softmax: fp32 scores -> fp16 attn ----------------
__global__ void __launch_bounds__(256) softmax_kernel(const float* __restrict__ s,
                                                      f16* __restrict__ ah) {
    const float* sr = s + (size_t)blockIdx.x * T_;
    f16* ahr = ah + (size_t)blockIdx.x * T_;
    int tid = threadIdx.x;
    float vl[8];
    float m = -1e30f;
    #pragma unroll
    for (int i = 0; i < 8; i++) { vl[i] = sr[tid + (i << 8)]; m = fmaxf(m, vl[i]); }
    #pragma unroll
    for (int o = 16; o; o >>= 1) m = fmaxf(m, __shfl_xor_sync(0xffffffffu, m, o));
    __shared__ float rmax[8], rsum[8];
    if ((tid & 31) == 0) rmax[tid >> 5] = m;
    __syncthreads();
    if (tid == 0) {
        float mm = rmax[0];
        for (int i = 1; i < 8; i++) mm = fmaxf(mm, rmax[i]);
        rmax[0] = mm;
    }
    __syncthreads();
    m = rmax[0];
    float sum = 0.f;
    #pragma unroll
    for (int i = 0; i < 8; i++) { vl[i] = __expf(vl[i] - m); sum += vl[i]; }
    #pragma unroll
    for (int o = 16; o; o >>= 1) sum += __shfl_xor_sync(0xffffffffu, sum, o);
    if ((tid & 31) == 0) rsum[tid >> 5] = sum;
    __syncthreads();
    if (tid == 0) {
        float ss = rsum[0];
        for (int i = 1; i < 8; i++) ss += rsum[i];
        rsum[0] = ss;
    }
    __syncthreads();
    float inv = 1.0f / rsum[0];
    #pragma unroll
    for (int i = 0; i < 8; i++)
        ahr[tid + (i << 8)] = __float2half_rn(vl[i] * inv);
}

// ---------------- AV: ao = attn @ v ----------------
__global__ void __launch_bounds__(256, 2) mm_av(const f16* ath,
                                                const f16* vth, const f16* vtl,
                                                f16* aoh) {
    int bh = blockIdx.z, b = bh >> 3, h = bh & 7;
    int m0 = blockIdx.y * 128;
    float acc[2][8][4];
    mm2_body(ath + (size_t)bh * T_ * T_, T_, m0, T_,
             vth + (size_t)bh * DK_ * T_, vtl + (size_t)bh * DK_ * T_, T_, 0, DK_,
             T_, acc);
    ACC_PAIRS(
        size_t idx = ((size_t)(b * T_ + m0 + rl)) * D_ + h * DK_ + cl;
        *(__half2*)&aoh[idx] = __halves2half2(__float2half_rn(v0), __float2half_rn(v1));
    );
}

// ---------------- output projection ----------------
__global__ void __launch_bounds__(256, 2) mm_out(const f16* aoh,
                                                 const f16* woh, const f16* wol,
                                                 float* __restrict__ out) {
    int m0 = blockIdx.y * 128, n0 = blockIdx.x * 128;
    float acc[2][8][4];
    mm2_body(aoh, D_, m0, BT_, woh, wol, D_, n0, D_, D_, acc);
    ACC_PAIRS(
        *(float2*)&out[(size_t)(m0 + rl) * D_ + n0 + cl] = make_float2(v0, v1);
    );
}

// ---------------- launch ----------------
extern "C" void kernel_launch(void* const* d_in, const int* in_sizes, int n_in,
                              void* d_out, int out_size) {
    (void)in_sizes; (void)n_in; (void)out_size;
    const float* x  = (const float*)d_in[0];
    const float* pe = (const float*)d_in[1];
    const float* Wq = (const float*)d_in[2];
    const float* Wk = (const float*)d_in[3];
    const float* Wv = (const float*)d_in[4];
    const float* Wo = (const float*)d_in[5];
    const float* Wp = (const float*)d_in[6];
    const float* bu = (const float*)d_in[7];
    const float* bv = (const float*)d_in[8];

    f16 *xh, *peh, *wqh, *wql, *wkh, *wkl, *wvh, *wvl, *woh, *wol, *wph, *wpl;
    f16 *quh, *qvh, *kh, *kl, *ph, *pl, *vth, *vtl, *ath, *aoh;
    float *v, *s;
    cudaGetSymbolAddress((void**)&xh,  g_xh);
    cudaGetSymbolAddress((void**)&peh, g_peh);
    cudaGetSymbolAddress((void**)&wqh, g_wqh); cudaGetSymbolAddress((void**)&wql, g_wql);
    cudaGetSymbolAddress((void**)&wkh, g_wkh); cudaGetSymbolAddress((void**)&wkl, g_wkl);
    cudaGetSymbolAddress((void**)&wvh, g_wvh); cudaGetSymbolAddress((void**)&wvl, g_wvl);
    cudaGetSymbolAddress((void**)&woh, g_woh); cudaGetSymbolAddress((void**)&wol, g_wol);
    cudaGetSymbolAddress((void**)&wph, g_wph); cudaGetSymbolAddress((void**)&wpl, g_wpl);
    cudaGetSymbolAddress((void**)&quh, g_quh); cudaGetSymbolAddress((void**)&qvh, g_qvh);
    cudaGetSymbolAddress((void**)&kh,  g_kh);  cudaGetSymbolAddress((void**)&kl,  g_kl);
    cudaGetSymbolAddress((void**)&ph,  g_ph);  cudaGetSymbolAddress((void**)&pl,  g_pl);
    cudaGetSymbolAddress((void**)&vth, g_vth); cudaGetSymbolAddress((void**)&vtl, g_vtl);
    cudaGetSymbolAddress((void**)&ath, g_ath);
    cudaGetSymbolAddress((void**)&aoh, g_aoh);
    cudaGetSymbolAddress((void**)&v,   g_v);
    cudaGetSymbolAddress((void**)&s,   g_s);

    cudaFuncSetAttribute(mm_proj,   cudaFuncAttributeMaxDynamicSharedMemorySize, SMEMSZ);
    cudaFuncSetAttribute(scores_ac, cudaFuncAttributeMaxDynamicSharedMemorySize, SMEMSZ);
    cudaFuncSetAttribute(scores_bd, cudaFuncAttributeMaxDynamicSharedMemorySize, SMEMSZ);
    cudaFuncSetAttribute(mm_av,     cudaFuncAttributeMaxDynamicSharedMemorySize, SMEMSZ);
    cudaFuncSetAttribute(mm_out,    cudaFuncAttributeMaxDynamicSharedMemorySize, SMEMSZ);

    // convert A-role inputs to fp16; split B-role weights to fp16 hi/lo
    cvt_h<<<(BT_ * D_ / 4 + 255) / 256, 256>>>(x,  xh,  BT_ * D_);
    cvt_h<<<(P_ * D_ / 4 + 255) / 256, 256>>>(pe, peh, P_ * D_);
    splitk<<<(D_ * D_ / 4 + 255) / 256, 256>>>(Wq, wqh, wql, D_ * D_);
    splitk<<<(D_ * D_ / 4 + 255) / 256, 256>>>(Wk, wkh, wkl, D_ * D_);
    splitk<<<(D_ * D_ / 4 + 255) / 256, 256>>>(Wv, wvh, wvl, D_ * D_);
    splitk<<<(D_ * D_ / 4 + 255) / 256, 256>>>(Wo, woh, wol, D_ * D_);
    splitk<<<(D_ * D_ / 4 + 255) / 256, 256>>>(Wp, wph, wpl, D_ * D_);

    // projections (fused bias add + convert in epilogue)
    mm_proj<<<dim3(D_ / 128, BT_ / 128, 4), 256, SMEMSZ>>>(
        xh, peh, wqh, wql, wkh, wkl, wvh, wvl, wph, wpl,
        bu, bv, quh, qvh, kh, kl, v, ph, pl);

    // v transpose + split
    vtrans<<<dim3(T_ / 32, DK_ / 32, B_ * H_), 256>>>(v, vth, vtl);

    // scores: AC GEMM then banded BD GEMM in diagonal coordinates
    scores_ac<<<dim3(T_ / 128, T_ / 128, B_ * H_), 256, SMEMSZ>>>(quh, kh, kl, s);
    scores_bd<<<dim3(17, T_ / 128, B_ * H_), 256, SMEMSZ>>>(qvh, ph, pl, s);

    // softmax -> fp16 attn
    softmax_kernel<<<B_ * H_ * T_, 256>>>(s, ath);

    // attn @ v
    mm_av<<<dim3(1, T_ / 128, B_ * H_), 256, SMEMSZ>>>(ath, vth, vtl, aoh);

    // output projection
    mm_out<<<dim3(D_ / 128, BT_ / 128, 1), 256, SMEMSZ>>>(aoh, woh, wol, (float*)d_out);
}

// round 12
// speedup vs baseline: 3.6838x; 1.2862x over previous
#include <cuda_runtime.h>
#include <cuda_fp16.h>
#include <stdint.h>
#include <math.h>

#define B_  4
#define T_  2048
#define D_  1024
#define H_  8
#define DK_ 128
#define P_  (2*T_-1)
#define BT_ (B_*T_)
#define BDW 2304            // bd band row width (floats)

typedef __half f16;

// ---------------- scratch (device globals: allocation-free) ----------------
static __device__ __align__(16) f16 g_xh [(size_t)BT_ * D_];
static __device__ __align__(16) f16 g_peh[(size_t)P_ * D_];
static __device__ __align__(16) f16 g_wqh[(size_t)D_ * D_], g_wql[(size_t)D_ * D_];
static __device__ __align__(16) f16 g_wkh[(size_t)D_ * D_], g_wkl[(size_t)D_ * D_];
static __device__ __align__(16) f16 g_wvh[(size_t)D_ * D_], g_wvl[(size_t)D_ * D_];
static __device__ __align__(16) f16 g_woh[(size_t)D_ * D_], g_wol[(size_t)D_ * D_];
static __device__ __align__(16) f16 g_wph[(size_t)D_ * D_], g_wpl[(size_t)D_ * D_];
static __device__ __align__(16) f16 g_quh[(size_t)BT_ * D_];
static __device__ __align__(16) f16 g_qvh[(size_t)BT_ * D_];
static __device__ __align__(16) f16 g_kh [(size_t)BT_ * D_], g_kl [(size_t)BT_ * D_];
static __device__ __align__(16) f16 g_ph [(size_t)P_ * D_],  g_pl [(size_t)P_ * D_];
static __device__ __align__(16) float g_v [(size_t)BT_ * D_];
static __device__ __align__(16) f16 g_vth[(size_t)B_ * H_ * DK_ * T_];
static __device__ __align__(16) f16 g_vtl[(size_t)B_ * H_ * DK_ * T_];
static __device__ __align__(16) float g_bd[(size_t)B_ * H_ * T_ * BDW];   // rel-pos band, k-aligned
static __device__ __align__(16) f16 g_aoh[(size_t)BT_ * D_];

// ============================ helpers ============================
__device__ __forceinline__ uint32_t smem_u32(const void* p) {
    uint32_t a;
    asm("{ .reg .u64 t; cvta.to.shared.u64 t, %1; cvt.u32.u64 %0, t; }" : "=r"(a) : "l"(p));
    return a;
}

__device__ __forceinline__ void split2h(float a, float b, __half2& h, __half2& l) {
    f16 ha = __float2half_rn(a), hb = __float2half_rn(b);
    h = __halves2half2(ha, hb);
    l = __halves2half2(__float2half_rn(a - __half2float(ha)),
                       __float2half_rn(b - __half2float(hb)));
}

__device__ __forceinline__ uint32_t pkh2(float a, float b) {
    __half2 h = __halves2half2(__float2half_rn(a), __float2half_rn(b));
    return *(uint32_t*)&h;
}

#define LDSM4(r0, r1, r2, r3, addr) \
    asm volatile("ldmatrix.sync.aligned.m8n8.x4.shared.b16 {%0,%1,%2,%3}, [%4];" \
        : "=r"(r0), "=r"(r1), "=r"(r2), "=r"(r3) : "r"(addr))

#define MMA16816(c, a, b0, b1) \
    asm volatile("mma.sync.aligned.m16n8k16.row.col.f32.f16.f16.f32 " \
        "{%0,%1,%2,%3}, {%4,%5,%6,%7}, {%8,%9}, {%0,%1,%2,%3};" \
        : "+f"((c)[0]), "+f"((c)[1]), "+f"((c)[2]), "+f"((c)[3]) \
        : "r"((a)[0]), "r"((a)[1]), "r"((a)[2]), "r"((a)[3]), "r"(b0), "r"(b1))

#define CP16(dst, src, sz) \
    asm volatile("cp.async.cg.shared.global [%0], [%1], 16, %2;" \
        :: "r"(dst), "l"(src), "r"(sz))
#define CP_COMMIT() asm volatile("cp.async.commit_group;")
#define CP_WAIT(n)  asm volatile("cp.async.wait_group %0;" :: "n"(n))

// ---------------- convert fp32 -> fp16 ----------------
__global__ void __launch_bounds__(256) cvt_h(const float* __restrict__ s,
                                             f16* __restrict__ h, int n) {
    int i = (blockIdx.x * 256 + threadIdx.x) * 4;
    if (i >= n) return;
    float4 v = *(const float4*)&s[i];
    *(__half2*)&h[i]     = __halves2half2(__float2half_rn(v.x), __float2half_rn(v.y));
    *(__half2*)&h[i + 2] = __halves2half2(__float2half_rn(v.z), __float2half_rn(v.w));
}

// ---------------- split fp32 -> fp16 hi/lo ----------------
__global__ void __launch_bounds__(256) splitk(const float* __restrict__ s,
                                              f16* __restrict__ h, f16* __restrict__ l,
                                              int n) {
    int i = (blockIdx.x * 256 + threadIdx.x) * 4;
    if (i >= n) return;
    float4 v = *(const float4*)&s[i];
    __half2 h0, l0, h1, l1;
    split2h(v.x, v.y, h0, l0);
    split2h(v.z, v.w, h1, l1);
    *(__half2*)&h[i]     = h0;
    *(__half2*)&h[i + 2] = h1;
    *(__half2*)&l[i]     = l0;
    *(__half2*)&l[i + 2] = l1;
}

// ======== warp-MMA NT GEMM: 128x128 tile, A fp16, B fp16 hi/lo, 2 passes ========
#define KC    32
#define LDST  40
#define ARRB  (128 * LDST * 2)
#define SS    (3 * ARRB)
#define NSTG  3
#define SMEMSZ (NSTG * SS)
#define OFF_AH 0
#define OFF_BH ARRB
#define OFF_BL (2 * ARRB)

__device__ __forceinline__ void mm2_body(
        const f16* __restrict__ Ah, int lda, int m0, int Mrows,
        const f16* __restrict__ Bh, const f16* __restrict__ Bl, int ldb, int n0, int Nrows,
        int K, float acc[2][8][4]) {
    extern __shared__ char dsm[];
    uint32_t sb = smem_u32(dsm);
    int tid = threadIdx.x, lane = tid & 31, wid = tid >> 5;
    int wm = (wid & 3) * 32, wn = (wid >> 2) * 64;
    int lr = lane & 15, lc8 = (lane >> 4) << 3;

    #pragma unroll
    for (int mt = 0; mt < 2; mt++)
        #pragma unroll
        for (int nt = 0; nt < 8; nt++)
            #pragma unroll
            for (int e = 0; e < 4; e++) acc[mt][nt][e] = 0.f;

    auto stage_fill = [&](int st, int kc) {
        uint32_t base = sb + st * SS;
        #pragma unroll
        for (int i = 0; i < 6; i++) {
            int sidx = tid + (i << 8);
            int arr = sidx >> 9;
            int rem = sidx & 511;
            int row = rem >> 2, seg = rem & 3;
            uint32_t doff = arr * ARRB + row * (LDST * 2) + seg * 16;
            const char* src;
            int sz;
            if (arr == 0) {
                int r = m0 + row;
                src = (const char*)(Ah + (size_t)r * lda + kc) + seg * 16;
                sz = (r < Mrows) ? 16 : 0;
            } else if (arr == 1) {
                int r = n0 + row;
                src = (const char*)(Bh + (size_t)r * ldb + kc) + seg * 16;
                sz = (r < Nrows) ? 16 : 0;
            } else {
                int r = n0 + row;
                src = (const char*)(Bl + (size_t)r * ldb + kc) + seg * 16;
                sz = (r < Nrows) ? 16 : 0;
            }
            CP16(base + doff, src, sz);
        }
    };

    const int NC = K / KC;
    stage_fill(0, 0);
    CP_COMMIT();
    if (NC > 1) { stage_fill(1, KC); CP_COMMIT(); }

    for (int c = 0; c < NC; c++) {
        if (c < NC - 1) CP_WAIT(1); else CP_WAIT(0);
        __syncthreads();

        uint32_t abase = sb + (c % NSTG) * SS;
        #pragma unroll
        for (int kk = 0; kk < KC; kk += 16) {
            uint32_t ah[2][4];
            #pragma unroll
            for (int mt = 0; mt < 2; mt++) {
                uint32_t r = abase + OFF_AH + (wm + mt * 16 + lr) * (LDST * 2) + (kk + lc8) * 2;
                LDSM4(ah[mt][0], ah[mt][1], ah[mt][2], ah[mt][3], r);
            }
            #pragma unroll
            for (int g = 0; g < 4; g++) {
                uint32_t bh0, bh1, bh2, bh3, bl0, bl1, bl2, bl3;
                uint32_t r = abase + OFF_BH + (wn + g * 16 + lr) * (LDST * 2) + (kk + lc8) * 2;
                LDSM4(bh0, bh1, bh2, bh3, r);
                r = abase + OFF_BL + (wn + g * 16 + lr) * (LDST * 2) + (kk + lc8) * 2;
                LDSM4(bl0, bl1, bl2, bl3, r);
                #pragma unroll
                for (int mt = 0; mt < 2; mt++) {
                    MMA16816(acc[mt][2 * g],     ah[mt], bh0, bh2);
                    MMA16816(acc[mt][2 * g + 1], ah[mt], bh1, bh3);
                    MMA16816(acc[mt][2 * g],     ah[mt], bl0, bl2);
                    MMA16816(acc[mt][2 * g + 1], ah[mt], bl1, bl3);
                }
            }
        }
        if (c + 2 < NC) { stage_fill((c + 2) % NSTG, (c + 2) * KC); CP_COMMIT(); }
    }
}

#define ACC_PAIRS(...) do {                                                   \
    int lane = threadIdx.x & 31, wid = threadIdx.x >> 5;                      \
    int wm = (wid & 3) * 32, wn = (wid >> 2) * 64;                            \
    int g = lane >> 2, tg = lane & 3;                                         \
    _Pragma("unroll") for (int mt = 0; mt < 2; mt++)                          \
    _Pragma("unroll") for (int hf = 0; hf < 2; hf++) {                        \
        int rl = wm + mt * 16 + g + hf * 8;                                   \
        _Pragma("unroll") for (int nt = 0; nt < 8; nt++) {                    \
            int cl = wn + nt * 8 + tg * 2;                                    \
            float v0 = acc[mt][nt][hf * 2], v1 = acc[mt][nt][hf * 2 + 1];     \
            { __VA_ARGS__ }                                                   \
        }                                                                     \
    }                                                                         \
} while (0)

// ---------------- projections: z=0 q(+biases), 1 k, 2 v, 3 p ----------------
__global__ void __launch_bounds__(256, 2) mm_proj(
        const f16* xh, const f16* peh,
        const f16* wqh, const f16* wql, const f16* wkh, const f16* wkl,
        const f16* wvh, const f16* wvl, const f16* wph, const f16* wpl,
        const float* bu, const float* bv,
        f16* quh, f16* qvh, f16* kh, f16* kl, float* v, f16* ph, f16* pl) {
    int z = blockIdx.z;
    const f16* Ah = (z == 3) ? peh : xh;
    const f16* Bh = (z == 0) ? wqh : (z == 1) ? wkh : (z == 2) ? wvh : wph;
    const f16* Bl = (z == 0) ? wql : (z == 1) ? wkl : (z == 2) ? wvl : wpl;
    int M = (z == 3) ? P_ : BT_;
    int m0 = blockIdx.y * 128;
    if (m0 >= M) return;
    int n0 = blockIdx.x * 128;
    float acc[2][8][4];
    mm2_body(Ah, D_, m0, M, Bh, Bl, D_, n0, D_, D_, acc);

    if (z == 0) {
        ACC_PAIRS(
            int r = m0 + rl, c = n0 + cl;
            size_t idx = (size_t)r * D_ + c;
            *(__half2*)&quh[idx] = __halves2half2(
                __float2half_rn(v0 + __ldg(&bu[c])), __float2half_rn(v1 + __ldg(&bu[c + 1])));
            *(__half2*)&qvh[idx] = __halves2half2(
                __float2half_rn(v0 + __ldg(&bv[c])), __float2half_rn(v1 + __ldg(&bv[c + 1])));
        );
    } else if (z == 1) {
        ACC_PAIRS(
            size_t idx = (size_t)(m0 + rl) * D_ + n0 + cl;
            __half2 h, l;
            split2h(v0, v1, h, l);
            *(__half2*)&kh[idx] = h; *(__half2*)&kl[idx] = l;
        );
    } else if (z == 2) {
        ACC_PAIRS(
            *(float2*)&v[(size_t)(m0 + rl) * D_ + n0 + cl] = make_float2(v0, v1);
        );
    } else {
        ACC_PAIRS(
            int r = m0 + rl;
            if (r < P_) {
                size_t idx = (size_t)r * D_ + n0 + cl;
                __half2 h, l;
                split2h(v0, v1, h, l);
                *(__half2*)&ph[idx] = h; *(__half2*)&pl[idx] = l;
            }
        );
    }
}

// ---- scores BD diag GEMM, k-aligned pure write: bd[q][k+128] = (q+v)·p[k-q+T-1]
__global__ void __launch_bounds__(256, 2) scores_bd(const f16* qvh,
                                                    const f16* ph, const f16* pl,
                                                    float* __restrict__ bd) {
    int bh = blockIdx.z, b = bh >> 3, h = bh & 7;
    int qi = blockIdx.y;
    int j0 = (15 - qi + (int)blockIdx.x) * 128;
    size_t abase = (size_t)b * T_ * D_ + h * DK_;
    int m0 = qi * 128;
    float acc[2][8][4];
    mm2_body(qvh + abase, D_, m0, T_, ph + h * DK_, pl + h * DK_, D_, j0, P_, DK_, acc);
    float* bdo = bd + (size_t)bh * T_ * BDW;
    ACC_PAIRS(
        int q = m0 + rl;
        int c = j0 + cl + q - 1919;           // c = k + 128, in [1, 2303]
        float* row = &bdo[(size_t)q * BDW];
        row[c] = v0; row[c + 1] = v1;
    );
}

// ---------------- v transpose + split: vt[bh][dk][t] ----------------
__global__ void __launch_bounds__(256) vtrans(const float* __restrict__ v,
                                              f16* __restrict__ vth,
                                              f16* __restrict__ vtl) {
    __shared__ float tile[32][33];
    int bh = blockIdx.z, b = bh >> 3, h = bh & 7;
    int t0 = blockIdx.x * 32, d0 = blockIdx.y * 32;
    int tx = threadIdx.x & 31, ty = threadIdx.x >> 5;
    #pragma unroll
    for (int i = 0; i < 4; ++i) {
        int t = t0 + ty + i * 8;
        tile[ty + i * 8][tx] = v[(size_t)(b * T_ + t) * D_ + h * DK_ + d0 + tx];
    }
    __syncthreads();
    #pragma unroll
    for (int i = 0; i < 4; ++i) {
        int dk = d0 + ty + i * 8;
        float val = tile[tx][ty + i * 8];
        f16 hv = __float2half_rn(val);
        size_t idx = ((size_t)bh * DK_ + dk) * T_ + t0 + tx;
        vth[idx] = hv;
        vtl[idx] = __float2half_rn(val - __half2float(hv));
    }
}

// ======== flash attention core: QK(2-pass) + bd + online softmax + PV(2-pass) ========
// block = 256 thr (8 warps x 16 q-rows), q-tile 128, streams 16 k-tiles.
#define LDSTF 136
#define FARR  (128 * LDSTF * 2)      // 34816
#define FSLOT (2 * FARR)             // 69632 (hi + lo)
#define FSMEM (3 * FSLOT)            // 208896

__global__ void __launch_bounds__(256, 1) flash_kernel(
        const f16* __restrict__ quh,
        const f16* __restrict__ kh, const f16* __restrict__ kl,
        const f16* __restrict__ vth, const f16* __restrict__ vtl,
        const float* __restrict__ bd, f16* __restrict__ aoh) {
    extern __shared__ char dsm[];
    uint32_t sb = smem_u32(dsm);
    int qt = blockIdx.x, bh = blockIdx.y, b = bh >> 3, h = bh & 7;
    int q0 = qt * 128;
    int tid = threadIdx.x, lane = tid & 31, wid = tid >> 5;
    int wm = wid * 16;
    int g = lane >> 2, tg = lane & 3;
    int lr = lane & 15, lc8 = (lane >> 4) << 3;

    // qu fragments resident in registers (8 dk16 chunks)
    const f16* qbase = quh + ((size_t)(b * T_ + q0 + wm)) * D_ + h * DK_;
    uint32_t quf[8][4];
    #pragma unroll
    for (int kk = 0; kk < 8; kk++) {
        quf[kk][0] = *(const uint32_t*)(qbase + (size_t)g * D_ + kk * 16 + 2 * tg);
        quf[kk][1] = *(const uint32_t*)(qbase + (size_t)(g + 8) * D_ + kk * 16 + 2 * tg);
        quf[kk][2] = *(const uint32_t*)(qbase + (size_t)g * D_ + kk * 16 + 2 * tg + 8);
        quf[kk][3] = *(const uint32_t*)(qbase + (size_t)(g + 8) * D_ + kk * 16 + 2 * tg + 8);
    }

    float O[16][4];
    #pragma unroll
    for (int nt = 0; nt < 16; nt++)
        #pragma unroll
        for (int e = 0; e < 4; e++) O[nt][e] = 0.f;
    float mrow0 = -1e30f, mrow1 = -1e30f, lrow0 = 0.f, lrow1 = 0.f;

    auto stage = [&](int slot, int kt, int kind) {
        uint32_t base = sb + slot * FSLOT;
        const f16 *sh, *sl;
        size_t stride;
        if (kind == 0) {
            sh = kh + ((size_t)(b * T_ + kt * 128)) * D_ + h * DK_;
            sl = kl + ((size_t)(b * T_ + kt * 128)) * D_ + h * DK_;
            stride = D_;
        } else {
            sh = vth + (size_t)bh * DK_ * T_ + kt * 128;
            sl = vtl + (size_t)bh * DK_ * T_ + kt * 128;
            stride = T_;
        }
        #pragma unroll
        for (int i = 0; i < 8; i++) {
            int idx = tid + (i << 8);
            int row = idx >> 4, seg = idx & 15;
            uint32_t doff = row * (LDSTF * 2) + seg * 16;
            CP16(base + doff,        (const char*)(sh + (size_t)row * stride) + seg * 16, 16);
            CP16(base + FARR + doff, (const char*)(sl + (size_t)row * stride) + seg * 16, 16);
        }
    };

    const float scale = 0.08838834764831845f;
    const float* bdr0 = bd + ((size_t)bh * T_ + q0 + wm + g) * BDW + 2 * tg + 128;
    const float* bdr1 = bdr0 + (size_t)8 * BDW;

    stage(0, 0, 0); CP_COMMIT();
    stage(1, 0, 1); CP_COMMIT();

    for (int kt = 0; kt < 16; kt++) {
        int sK = (2 * kt) % 3, sV = (2 * kt + 1) % 3;
        if (kt < 15) { stage((2 * kt + 2) % 3, kt + 1, 0); CP_COMMIT(); CP_WAIT(2); }
        else CP_WAIT(1);
        __syncthreads();

        // ---- QK: S = qu · K^T (hi + lo passes) ----
        float S[16][4];
        #pragma unroll
        for (int nt = 0; nt < 16; nt++)
            #pragma unroll
            for (int e = 0; e < 4; e++) S[nt][e] = 0.f;
        uint32_t kb = sb + sK * FSLOT;
        #pragma unroll
        for (int kk = 0; kk < 8; kk++) {
            #pragma unroll
            for (int gg = 0; gg < 8; gg++) {
                uint32_t b0, b1, b2, b3, c0, c1, c2, c3;
                uint32_t r = kb + (gg * 16 + lr) * (LDSTF * 2) + (kk * 16 + lc8) * 2;
                LDSM4(b0, b1, b2, b3, r);
                LDSM4(c0, c1, c2, c3, r + FARR);
                MMA16816(S[2 * gg],     quf[kk], b0, b2);
                MMA16816(S[2 * gg + 1], quf[kk], b1, b3);
                MMA16816(S[2 * gg],     quf[kk], c0, c2);
                MMA16816(S[2 * gg + 1], quf[kk], c1, c3);
            }
        }

        // ---- add rel-pos band + scale, row max ----
        float mx0 = -1e30f, mx1 = -1e30f;
        #pragma unroll
        for (int nt = 0; nt < 16; nt++) {
            float2 d0 = *(const float2*)(bdr0 + kt * 128 + nt * 8);
            float2 d1 = *(const float2*)(bdr1 + kt * 128 + nt * 8);
            S[nt][0] = (S[nt][0] + d0.x) * scale;
            S[nt][1] = (S[nt][1] + d0.y) * scale;
            S[nt][2] = (S[nt][2] + d1.x) * scale;
            S[nt][3] = (S[nt][3] + d1.y) * scale;
            mx0 = fmaxf(mx0, fmaxf(S[nt][0], S[nt][1]));
            mx1 = fmaxf(mx1, fmaxf(S[nt][2], S[nt][3]));
        }
        mx0 = fmaxf(mx0, __shfl_xor_sync(0xffffffffu, mx0, 1));
        mx0 = fmaxf(mx0, __shfl_xor_sync(0xffffffffu, mx0, 2));
        mx1 = fmaxf(mx1, __shfl_xor_sync(0xffffffffu, mx1, 1));
        mx1 = fmaxf(mx1, __shfl_xor_sync(0xffffffffu, mx1, 2));
        float mn0 = fmaxf(mrow0, mx0), mn1 = fmaxf(mrow1, mx1);
        float sc0 = __expf(mrow0 - mn0), sc1 = __expf(mrow1 - mn1);
        mrow0 = mn0; mrow1 = mn1;

        // ---- exp + pack P fragments + row sum ----
        float sum0 = 0.f, sum1 = 0.f;
        uint32_t pf[8][4];
        #pragma unroll
        for (int kk = 0; kk < 8; kk++) {
            float e00 = __expf(S[2 * kk][0] - mn0),     e01 = __expf(S[2 * kk][1] - mn0);
            float e02 = __expf(S[2 * kk][2] - mn1),     e03 = __expf(S[2 * kk][3] - mn1);
            float e10 = __expf(S[2 * kk + 1][0] - mn0), e11 = __expf(S[2 * kk + 1][1] - mn0);
            float e12 = __expf(S[2 * kk + 1][2] - mn1), e13 = __expf(S[2 * kk + 1][3] - mn1);
            sum0 += e00 + e01 + e10 + e11;
            sum1 += e02 + e03 + e12 + e13;
            pf[kk][0] = pkh2(e00, e01);
            pf[kk][1] = pkh2(e02, e03);
            pf[kk][2] = pkh2(e10, e11);
            pf[kk][3] = pkh2(e12, e13);
        }
        sum0 += __shfl_xor_sync(0xffffffffu, sum0, 1);
        sum0 += __shfl_xor_sync(0xffffffffu, sum0, 2);
        sum1 += __shfl_xor_sync(0xffffffffu, sum1, 1);
        sum1 += __shfl_xor_sync(0xffffffffu, sum1, 2);
        lrow0 = lrow0 * sc0 + sum0;
        lrow1 = lrow1 * sc1 + sum1;
        #pragma unroll
        for (int nt = 0; nt < 16; nt++) {
            O[nt][0] *= sc0; O[nt][1] *= sc0;
            O[nt][2] *= sc1; O[nt][3] *= sc1;
        }

        if (kt < 15) { stage(sK, kt + 1, 1); CP_COMMIT(); CP_WAIT(2); }
        else CP_WAIT(0);
        __syncthreads();

        // ---- PV: O += P · V^T (hi + lo passes) ----
        uint32_t vb = sb + sV * FSLOT;
        #pragma unroll
        for (int kk = 0; kk < 8; kk++) {
            #pragma unroll
            for (int gg = 0; gg < 8; gg++) {
                uint32_t b0, b1, b2, b3, c0, c1, c2, c3;
                uint32_t r = vb + (gg * 16 + lr) * (LDSTF * 2) + (kk * 16 + lc8) * 2;
                LDSM4(b0, b1, b2, b3, r);
                LDSM4(c0, c1, c2, c3, r + FARR);
                MMA16816(O[2 * gg],     pf[kk], b0, b2);
                MMA16816(O[2 * gg + 1], pf[kk], b1, b3);
                MMA16816(O[2 * gg],     pf[kk], c0, c2);
                MMA16816(O[2 * gg + 1], pf[kk], c1, c3);
            }
        }
        __syncthreads();
    }

    // ---- epilogue: normalize and write fp16 ----
    float inv0 = 1.f / lrow0, inv1 = 1.f / lrow1;
    f16* ob = aoh + ((size_t)(b * T_ + q0 + wm)) * D_ + h * DK_;
    #pragma unroll
    for (int nt = 0; nt < 16; nt++) {
        int c = nt * 8 + 2 * tg;
        *(__half2*)(ob + (size_t)g * D_ + c) =
            __halves2half2(__float2half_rn(O[nt][0] * inv0), __float2half_rn(O[nt][1] * inv0));
        *(__half2*)(ob + (size_t)(g + 8) * D_ + c) =
            __halves2half2(__float2half_rn(O[nt][2] * inv1), __float2half_rn(O[nt][3] * inv1));
    }
}

// ---------------- output projection ----------------
__global__ void __launch_bounds__(256, 2) mm_out(const f16* aoh,
                                                 const f16* woh, const f16* wol,
                                                 float* __restrict__ out) {
    int m0 = blockIdx.y * 128, n0 = blockIdx.x * 128;
    float acc[2][8][4];
    mm2_body(aoh, D_, m0, BT_, woh, wol, D_, n0, D_, D_, acc);
    ACC_PAIRS(
        *(float2*)&out[(size_t)(m0 + rl) * D_ + n0 + cl] = make_float2(v0, v1);
    );
}

// ---------------- launch ----------------
extern "C" void kernel_launch(void* const* d_in, const int* in_sizes, int n_in,
                              void* d_out, int out_size) {
    (void)in_sizes; (void)n_in; (void)out_size;
    const float* x  = (const float*)d_in[0];
    const float* pe = (const float*)d_in[1];
    const float* Wq = (const float*)d_in[2];
    const float* Wk = (const float*)d_in[3];
    const float* Wv = (const float*)d_in[4];
    const float* Wo = (const float*)d_in[5];
    const float* Wp = (const float*)d_in[6];
    const float* bu = (const float*)d_in[7];
    const float* bv = (const float*)d_in[8];

    f16 *xh, *peh, *wqh, *wql, *wkh, *wkl, *wvh, *wvl, *woh, *wol, *wph, *wpl;
    f16 *quh, *qvh, *kh, *kl, *ph, *pl, *vth, *vtl, *aoh;
    float *v, *bd;
    cudaGetSymbolAddress((void**)&xh,  g_xh);
    cudaGetSymbolAddress((void**)&peh, g_peh);
    cudaGetSymbolAddress((void**)&wqh, g_wqh); cudaGetSymbolAddress((void**)&wql, g_wql);
    cudaGetSymbolAddress((void**)&wkh, g_wkh); cudaGetSymbolAddress((void**)&wkl, g_wkl);
    cudaGetSymbolAddress((void**)&wvh, g_wvh); cudaGetSymbolAddress((void**)&wvl, g_wvl);
    cudaGetSymbolAddress((void**)&woh, g_woh); cudaGetSymbolAddress((void**)&wol, g_wol);
    cudaGetSymbolAddress((void**)&wph, g_wph); cudaGetSymbolAddress((void**)&wpl, g_wpl);
    cudaGetSymbolAddress((void**)&quh, g_quh); cudaGetSymbolAddress((void**)&qvh, g_qvh);
    cudaGetSymbolAddress((void**)&kh,  g_kh);  cudaGetSymbolAddress((void**)&kl,  g_kl);
    cudaGetSymbolAddress((void**)&ph,  g_ph);  cudaGetSymbolAddress((void**)&pl,  g_pl);
    cudaGetSymbolAddress((void**)&vth, g_vth); cudaGetSymbolAddress((void**)&vtl, g_vtl);
    cudaGetSymbolAddress((void**)&aoh, g_aoh);
    cudaGetSymbolAddress((void**)&v,   g_v);
    cudaGetSymbolAddress((void**)&bd,  g_bd);

    cudaFuncSetAttribute(mm_proj,      cudaFuncAttributeMaxDynamicSharedMemorySize, SMEMSZ);
    cudaFuncSetAttribute(scores_bd,    cudaFuncAttributeMaxDynamicSharedMemorySize, SMEMSZ);
    cudaFuncSetAttribute(mm_out,       cudaFuncAttributeMaxDynamicSharedMemorySize, SMEMSZ);
    cudaFuncSetAttribute(flash_kernel, cudaFuncAttributeMaxDynamicSharedMemorySize, FSMEM);

    cvt_h<<<(BT_ * D_ / 4 + 255) / 256, 256>>>(x,  xh,  BT_ * D_);
    cvt_h<<<(P_ * D_ / 4 + 255) / 256, 256>>>(pe, peh, P_ * D_);
    splitk<<<(D_ * D_ / 4 + 255) / 256, 256>>>(Wq, wqh, wql, D_ * D_);
    splitk<<<(D_ * D_ / 4 + 255) / 256, 256>>>(Wk, wkh, wkl, D_ * D_);
    splitk<<<(D_ * D_ / 4 + 255) / 256, 256>>>(Wv, wvh, wvl, D_ * D_);
    splitk<<<(D_ * D_ / 4 + 255) / 256, 256>>>(Wo, woh, wol, D_ * D_);
    splitk<<<(D_ * D_ / 4 + 255) / 256, 256>>>(Wp, wph, wpl, D_ * D_);

    mm_proj<<<dim3(D_ / 128, BT_ / 128, 4), 256, SMEMSZ>>>(
        xh, peh, wqh, wql, wkh, wkl, wvh, wvl, wph, wpl,
        bu, bv, quh, qvh, kh, kl, v, ph, pl);

    vtrans<<<dim3(T_ / 32, DK_ / 32, B_ * H_), 256>>>(v, vth, vtl);

    scores_bd<<<dim3(17, T_ / 128, B_ * H_), 256, SMEMSZ>>>(qvh, ph, pl, bd);

    flash_kernel<<<dim3(T_ / 128, B_ * H_), 256, FSMEM>>>(quh, kh, kl, vth, vtl, bd, aoh);

    mm_out<<<dim3(D_ / 128, BT_ / 128, 1), 256, SMEMSZ>>>(aoh, woh, wol, (float*)d_out);
}